// round 7
// baseline (speedup 1.0000x reference)
#include <cuda_runtime.h>
#include <math.h>

#define NB 4096
typedef unsigned long long u64;

__device__ __forceinline__ u64 pk2(float lo, float hi) {
    u64 r; asm("mov.b64 %0,{%1,%2};" : "=l"(r) : "f"(lo), "f"(hi)); return r;
}
__device__ __forceinline__ u64 dup2(float x) { return pk2(x, x); }
__device__ __forceinline__ void fm2(u64& d, u64 a, u64 b) {
    asm("fma.rn.f32x2 %0,%1,%2,%0;" : "+l"(d) : "l"(a), "l"(b));
}
__device__ __forceinline__ void up2(u64 v, float& a, float& b) {
    asm("mov.b64 {%0,%1},%2;" : "=f"(a), "=f"(b) : "l"(v));
}

// ---------------- scratch ----------------
__device__ float g_h1[NB * 32 * 196];
__device__ float g_h2[NB * 32 * 49];
__device__ float g_h3[NB * 1024];
__device__ float g_hf[NB * 256];
__device__ float g_z [NB * 20];
__device__ float g_f2[NB * 256];
__device__ float g_f3[NB * 1024];
__device__ float g_u1[NB * 32 * 49];
__device__ float g_u2[NB * 32 * 196];

#define MU_OFF   (NB * 784)
#define LS_OFF   (NB * 784 + NB * 20)

// ---------------- conv1 ----------------
__global__ void conv1_k(const float* __restrict__ x, const float* __restrict__ w,
                        const float* __restrict__ bias) {
    extern __shared__ float sm[];
    float* in_s = sm;          // 784
    float* w_s  = sm + 784;    // 512, [kk][oc]
    int b = blockIdx.x, tid = threadIdx.x;
    const float* xin = x + b * 784;
    for (int i = tid; i < 784; i += 256) in_s[i] = xin[i];
    for (int i = tid; i < 512; i += 256) { int oc = i & 31, kk = i >> 5; w_s[kk * 32 + oc] = w[oc * 16 + kk]; }
    __syncthreads();
    for (int u = tid; u < 784; u += 256) {
        int p = u >> 2, g = u & 3;
        int oy = p / 14, ox = p % 14;
        u64 acc[4];
        #pragma unroll
        for (int j = 0; j < 4; j++) acc[j] = pk2(bias[g * 8 + 2 * j], bias[g * 8 + 2 * j + 1]);
        #pragma unroll
        for (int ky = 0; ky < 4; ky++) {
            int iy = oy * 2 - 1 + ky;
            if (iy < 0 || iy >= 28) continue;
            #pragma unroll
            for (int kx = 0; kx < 4; kx++) {
                int ix = ox * 2 - 1 + kx;
                if (ix < 0 || ix >= 28) continue;
                u64 xd = dup2(in_s[iy * 28 + ix]);
                const ulonglong2* wq = (const ulonglong2*)(w_s + (ky * 4 + kx) * 32 + g * 8);
                ulonglong2 w0 = wq[0];
                fm2(acc[0], xd, w0.x); fm2(acc[1], xd, w0.y);
                ulonglong2 w1 = wq[1];
                fm2(acc[2], xd, w1.x); fm2(acc[3], xd, w1.y);
            }
        }
        #pragma unroll
        for (int j = 0; j < 4; j++) {
            float lo, hi; up2(acc[j], lo, hi);
            g_h1[(size_t)(b * 32 + g * 8 + 2 * j)     * 196 + p] = fmaxf(lo, 0.f);
            g_h1[(size_t)(b * 32 + g * 8 + 2 * j + 1) * 196 + p] = fmaxf(hi, 0.f);
        }
    }
}

// ---------------- conv2: 4 img/block, 800 threads, thread = (img,p,quarter:8oc) ----------------
__global__ void conv2_k(const float* __restrict__ w, const float* __restrict__ bias) {
    extern __shared__ float sm[];
    float* in_s = sm;            // 4*32*288 = 36864
    float* w_s  = sm + 36864;    // 512*36 = 18432, [ic*16+kk][oc]
    int b0 = blockIdx.x * 4, tid = threadIdx.x, nt = blockDim.x;
    float4* z4 = (float4*)in_s;
    for (int i = tid; i < 9216; i += nt) z4[i] = make_float4(0.f, 0.f, 0.f, 0.f);
    for (int i = tid; i < 16384; i += nt) {
        int oc = i & 31, rest = i >> 5;
        w_s[rest * 36 + oc] = w[oc * 512 + rest];
    }
    __syncthreads();
    for (int i = tid; i < 4 * 6272; i += nt) {
        int img = i / 6272, r = i % 6272;
        int ic = r / 196, q = r % 196, y = q / 14, xx = q % 14;
        in_s[(img * 32 + ic) * 288 + (y + 1) * 18 + (xx + 1)] = g_h1[(size_t)(b0 + img) * 6272 + r];
    }
    __syncthreads();
    if (tid >= 784) return;
    int img = tid / 196, rr = tid % 196;
    int p = rr % 49, quarter = rr / 49;
    int oy = p / 7, ox = p % 7;
    u64 acc[4];
    #pragma unroll
    for (int j = 0; j < 4; j++) acc[j] = pk2(bias[quarter * 8 + 2 * j], bias[quarter * 8 + 2 * j + 1]);
    for (int ic = 0; ic < 32; ic++) {
        const float* xs = in_s + (img * 32 + ic) * 288 + (oy * 2) * 18 + ox * 2;
        const float* wb = w_s + (ic * 16) * 36 + quarter * 8;
        #pragma unroll
        for (int kk = 0; kk < 16; kk++) {
            u64 xd = dup2(xs[(kk >> 2) * 18 + (kk & 3)]);
            const ulonglong2* wq = (const ulonglong2*)(wb + kk * 36);
            ulonglong2 w0 = wq[0];
            fm2(acc[0], xd, w0.x); fm2(acc[1], xd, w0.y);
            ulonglong2 w1 = wq[1];
            fm2(acc[2], xd, w1.x); fm2(acc[3], xd, w1.y);
        }
    }
    #pragma unroll
    for (int j = 0; j < 4; j++) {
        float lo, hi; up2(acc[j], lo, hi);
        g_h2[(size_t)((b0 + img) * 32 + quarter * 8 + 2 * j)     * 49 + p] = fmaxf(lo, 0.f);
        g_h2[(size_t)((b0 + img) * 32 + quarter * 8 + 2 * j + 1) * 49 + p] = fmaxf(hi, 0.f);
    }
}

// ---------------- conv3: 12 img/block, 768 threads, thread = (img,p,quarter:16oc) ----------------
__global__ void conv3_k(const float* __restrict__ w, const float* __restrict__ bias) {
    extern __shared__ float sm[];
    float* in_s = sm;            // 12*32*84 = 32256
    float* w_s  = sm + 32256;    // 288*68 = 19584, [ic*9+kk][oc]
    int b0 = blockIdx.x * 12, tid = threadIdx.x, nt = blockDim.x;
    int nimg = min(12, NB - b0);
    float4* z4 = (float4*)in_s;
    for (int i = tid; i < 8064; i += nt) z4[i] = make_float4(0.f, 0.f, 0.f, 0.f);
    for (int i = tid; i < 18432; i += nt) {
        int oc = i & 63, rest = i >> 6;
        w_s[rest * 68 + oc] = w[oc * 288 + rest];
    }
    __syncthreads();
    for (int i = tid; i < nimg * 1568; i += nt) {
        int img = i / 1568, r = i % 1568;
        int ic = r / 49, q = r % 49, y = q / 7, xx = q % 7;
        in_s[(img * 32 + ic) * 84 + (y + 1) * 9 + (xx + 1)] = g_h2[(size_t)(b0 + img) * 1568 + r];
    }
    __syncthreads();
    int img = tid / 64, rr = tid % 64;
    if (img >= nimg) return;
    int p = rr & 15, quarter = rr >> 4;
    int oy = p >> 2, ox = p & 3;
    u64 acc[8];
    #pragma unroll
    for (int j = 0; j < 8; j++) acc[j] = pk2(bias[quarter * 16 + 2 * j], bias[quarter * 16 + 2 * j + 1]);
    for (int ic = 0; ic < 32; ic++) {
        const float* xs = in_s + (img * 32 + ic) * 84 + (oy * 2) * 9 + ox * 2;
        const float* wb = w_s + (ic * 9) * 68 + quarter * 16;
        #pragma unroll
        for (int kk = 0; kk < 9; kk++) {
            u64 xd = dup2(xs[(kk / 3) * 9 + (kk % 3)]);
            const ulonglong2* wq = (const ulonglong2*)(wb + kk * 68);
            #pragma unroll
            for (int v = 0; v < 4; v++) {
                ulonglong2 wv = wq[v];
                fm2(acc[2 * v], xd, wv.x); fm2(acc[2 * v + 1], xd, wv.y);
            }
        }
    }
    #pragma unroll
    for (int j = 0; j < 8; j++) {
        float lo, hi; up2(acc[j], lo, hi);
        g_h3[(size_t)((b0 + img) * 64 + quarter * 16 + 2 * j)     * 16 + p] = fmaxf(lo, 0.f);
        g_h3[(size_t)((b0 + img) * 64 + quarter * 16 + 2 * j + 1) * 16 + p] = fmaxf(hi, 0.f);
    }
}

// ---------------- NT GEMM: BM=32, BN=64, BK=16, 256 threads (2x4 tile) ----------------
__global__ void gemm_k(const float* __restrict__ A, const float* __restrict__ W,
                       const float* __restrict__ bias, float* __restrict__ C,
                       int M, int N, int K, int relu) {
    __shared__ float As[16 * 36];
    __shared__ float Ws[16 * 68];
    int tid = threadIdx.x, tx = tid & 15, ty = tid >> 4;   // ty 0..15
    int m0 = blockIdx.y * 32, n0 = blockIdx.x * 64;
    u64 acc[2][2] = {};
    for (int kt = 0; kt < K; kt += 16) {
        #pragma unroll
        for (int i = 0; i < 2; i++) {
            int idx = tid + i * 256;
            int k = idx & 15, m = idx >> 4;
            As[k * 36 + m] = A[(size_t)(m0 + m) * K + kt + k];
        }
        #pragma unroll
        for (int i = 0; i < 4; i++) {
            int idx = tid + i * 256;
            int k = idx & 15, n = idx >> 4;
            Ws[k * 68 + n] = W[(size_t)(n0 + n) * K + kt + k];
        }
        __syncthreads();
        #pragma unroll
        for (int kk = 0; kk < 16; kk++) {
            float2 a = *(const float2*)&As[kk * 36 + ty * 2];
            ulonglong2 bv = *(const ulonglong2*)&Ws[kk * 68 + tx * 4];
            u64 a0 = dup2(a.x), a1 = dup2(a.y);
            fm2(acc[0][0], a0, bv.x); fm2(acc[0][1], a0, bv.y);
            fm2(acc[1][0], a1, bv.x); fm2(acc[1][1], a1, bv.y);
        }
        __syncthreads();
    }
    #pragma unroll
    for (int i = 0; i < 2; i++) {
        int m = m0 + ty * 2 + i;
        #pragma unroll
        for (int jp = 0; jp < 2; jp++) {
            float lo, hi; up2(acc[i][jp], lo, hi);
            int n = n0 + tx * 4 + 2 * jp;
            float v0 = lo + bias[n], v1 = hi + bias[n + 1];
            if (relu) { v0 = fmaxf(v0, 0.f); v1 = fmaxf(v1, 0.f); }
            C[(size_t)m * N + n] = v0;
            C[(size_t)m * N + n + 1] = v1;
        }
    }
}

// ---------------- latent ----------------
__global__ void latent_k(const float* __restrict__ w_mu, const float* __restrict__ b_mu,
                         const float* __restrict__ w_ls, const float* __restrict__ b_ls,
                         const float* __restrict__ eps, float* __restrict__ out) {
    int idx = blockIdx.x * 256 + threadIdx.x;
    if (idx >= NB * 20) return;
    int b = idx / 20, l = idx % 20;
    const float4* h4 = (const float4*)(g_hf + (size_t)b * 256);
    const float4* wm = (const float4*)(w_mu + (size_t)l * 256);
    const float4* wl = (const float4*)(w_ls + (size_t)l * 256);
    float sm_ = 0.f, sl_ = 0.f;
    #pragma unroll 8
    for (int k = 0; k < 64; k++) {
        float4 h = h4[k], a = wm[k], c = wl[k];
        sm_ += h.x * a.x + h.y * a.y + h.z * a.z + h.w * a.w;
        sl_ += h.x * c.x + h.y * c.y + h.z * c.z + h.w * c.w;
    }
    float mu = sm_ + b_mu[l];
    float ls = sl_ + b_ls[l];
    out[MU_OFF + idx] = mu;
    out[LS_OFF + idx] = ls;
    float m = mu, s = ls;
    #pragma unroll 4
    for (int i = 0; i < 100; i++) {
        m = m + 0.1f * m;
        s = s + 0.05f * (expf(s) - 1.0f);
    }
    g_z[idx] = eps[idx] * expf(0.5f * s) + m;
}

// ---------------- fc2 ----------------
__global__ void fc2_k(const float* __restrict__ w, const float* __restrict__ bias) {
    int idx = blockIdx.x * 256 + threadIdx.x;
    if (idx >= NB * 256) return;
    int b = idx >> 8, o = idx & 255;
    const float* z = g_z + (size_t)b * 20;
    const float* wr = w + (size_t)o * 20;
    float acc = bias[o];
    #pragma unroll
    for (int k = 0; k < 20; k++) acc += z[k] * wr[k];
    g_f2[idx] = fmaxf(acc, 0.f);
}

// ---------------- deconv1: 5 img/block, 992 threads, thread = (img,p,quarter:8oc) ----------------
__global__ void deconv1_k(const float* __restrict__ w, const float* __restrict__ bias) {
    extern __shared__ float sm[];
    float* in_s = sm;            // 5*1024
    float* w_s  = sm + 5120;     // 576*36 = 20736, [ic*9+kk][oc]
    int b0 = blockIdx.x * 5, tid = threadIdx.x, nt = blockDim.x;
    int nimg = min(5, NB - b0);
    for (int i = tid; i < nimg * 1024; i += nt) in_s[i] = g_f3[(size_t)b0 * 1024 + i];
    for (int i = tid; i < 18432; i += nt) {
        int oc = i & 31, rest = i >> 5;
        int ic = rest / 9, kk = rest % 9;
        w_s[rest * 36 + oc] = w[ic * 288 + oc * 9 + kk];
    }
    __syncthreads();
    if (tid >= 980) return;
    int img = tid / 196, rr = tid % 196;
    if (img >= nimg) return;
    int p = rr % 49, quarter = rr / 49;
    int oy = p / 7, ox = p % 7;
    int kyA = (oy & 1) ? 0 : 1;
    int iyA = (oy + 1 - kyA) >> 1;
    int vyB = oy & 1;
    int iyB = (oy >= 1) ? ((oy - 1) >> 1) : 0;
    int kxA = (ox & 1) ? 0 : 1;
    int ixA = (ox + 1 - kxA) >> 1;
    int vxB = ox & 1;
    int ixB = (ox >= 1) ? ((ox - 1) >> 1) : 0;
    int kyT[2] = {kyA, 2}, iyT[2] = {iyA, iyB};
    int kxT[2] = {kxA, 2}, ixT[2] = {ixA, ixB};
    int vy[2] = {1, vyB}, vx[2] = {1, vxB};
    u64 acc[4];
    #pragma unroll
    for (int j = 0; j < 4; j++) acc[j] = pk2(bias[quarter * 8 + 2 * j], bias[quarter * 8 + 2 * j + 1]);
    for (int ic = 0; ic < 64; ic++) {
        const float* xs = in_s + img * 1024 + ic * 16;
        #pragma unroll
        for (int a = 0; a < 2; a++) {
            #pragma unroll
            for (int bb = 0; bb < 2; bb++) {
                float xv = (vy[a] & vx[bb]) ? xs[iyT[a] * 4 + ixT[bb]] : 0.f;
                u64 xd = dup2(xv);
                const ulonglong2* wq = (const ulonglong2*)(w_s + (ic * 9 + kyT[a] * 3 + kxT[bb]) * 36 + quarter * 8);
                ulonglong2 w0 = wq[0];
                fm2(acc[0], xd, w0.x); fm2(acc[1], xd, w0.y);
                ulonglong2 w1 = wq[1];
                fm2(acc[2], xd, w1.x); fm2(acc[3], xd, w1.y);
            }
        }
    }
    #pragma unroll
    for (int j = 0; j < 4; j++) {
        float lo, hi; up2(acc[j], lo, hi);
        g_u1[(size_t)((b0 + img) * 32 + quarter * 8 + 2 * j)     * 49 + p] = fmaxf(lo, 0.f);
        g_u1[(size_t)((b0 + img) * 32 + quarter * 8 + 2 * j + 1) * 49 + p] = fmaxf(hi, 0.f);
    }
}

// ---------------- deconv2: 2 img/block, 800 threads, thread = (img,p,half:16oc) ----------------
__global__ void deconv2_k(const float* __restrict__ w, const float* __restrict__ bias) {
    extern __shared__ float sm[];
    float* in_s = sm;            // 2*32*84 = 5376
    float* w_s  = sm + 5376;     // 512*36 = 18432, [ic*16+kk][oc]
    int b0 = blockIdx.x * 2, tid = threadIdx.x, nt = blockDim.x;
    float4* z4 = (float4*)in_s;
    for (int i = tid; i < 1344; i += nt) z4[i] = make_float4(0.f, 0.f, 0.f, 0.f);
    for (int i = tid; i < 16384; i += nt) {
        int oc = i & 31, rest = i >> 5;
        w_s[rest * 36 + oc] = w[(rest >> 4) * 512 + oc * 16 + (rest & 15)];
    }
    __syncthreads();
    for (int i = tid; i < 2 * 1568; i += nt) {
        int img = i / 1568, r = i % 1568;
        int ic = r / 49, q = r % 49, y = q / 7, xx = q % 7;
        in_s[(img * 32 + ic) * 84 + (y + 1) * 9 + (xx + 1)] = g_u1[(size_t)(b0 + img) * 1568 + r];
    }
    __syncthreads();
    if (tid >= 784) return;
    int img = tid / 392, rr = tid % 392;
    int p = rr % 196, half = rr / 196;
    int oy = p / 14, ox = p % 14;
    int c = (oy + 1) & 1;
    int r0 = ((oy + 1 - c) >> 1) + 1;
    int d = (ox + 1) & 1;
    int c0 = ((ox + 1 - d) >> 1) + 1;
    u64 acc[8];
    #pragma unroll
    for (int j = 0; j < 8; j++) acc[j] = pk2(bias[half * 16 + 2 * j], bias[half * 16 + 2 * j + 1]);
    for (int ic = 0; ic < 32; ic++) {
        const float* xs = in_s + (img * 32 + ic) * 84;
        #pragma unroll
        for (int a = 0; a < 2; a++) {
            #pragma unroll
            for (int bb = 0; bb < 2; bb++) {
                u64 xd = dup2(xs[(r0 - a) * 9 + (c0 - bb)]);
                int kk = (c + 2 * a) * 4 + (d + 2 * bb);
                const ulonglong2* wq = (const ulonglong2*)(w_s + (ic * 16 + kk) * 36 + half * 16);
                #pragma unroll
                for (int v = 0; v < 4; v++) {
                    ulonglong2 wv = wq[v];
                    fm2(acc[2 * v], xd, wv.x); fm2(acc[2 * v + 1], xd, wv.y);
                }
            }
        }
    }
    #pragma unroll
    for (int j = 0; j < 8; j++) {
        float lo, hi; up2(acc[j], lo, hi);
        g_u2[(size_t)((b0 + img) * 32 + half * 16 + 2 * j)     * 196 + p] = fmaxf(lo, 0.f);
        g_u2[(size_t)((b0 + img) * 32 + half * 16 + 2 * j + 1) * 196 + p] = fmaxf(hi, 0.f);
    }
}

// ---------------- deconv3 (unchanged) ----------------
__global__ void deconv3_k(const float* __restrict__ w, const float* __restrict__ bias,
                          float* __restrict__ out) {
    extern __shared__ float sm[];
    float* in_s = sm;                    // 2*32*256 = 16384
    u64*   wpk  = (u64*)(sm + 16384);    // 256 u64
    int b0 = blockIdx.x * 2, tid = threadIdx.x, nt = blockDim.x;
    float4* z4 = (float4*)in_s;
    for (int i = tid; i < 4096; i += nt) z4[i] = make_float4(0.f, 0.f, 0.f, 0.f);
    for (int i = tid; i < 256; i += nt) {
        int t = i & 1, rest = i >> 1;
        int ic = rest & 31, ky = rest >> 5;
        wpk[(ky * 32 + ic) * 2 + t] = pk2(w[ic * 16 + ky * 4 + 2 * t + 1], w[ic * 16 + ky * 4 + 2 * t]);
    }
    __syncthreads();
    for (int i = tid; i < 2 * 6272; i += nt) {
        int img = i / 6272, r = i % 6272;
        int ic = r / 196, q = r % 196, y = q / 14, xx = q % 14;
        in_s[(img * 32 + ic) * 256 + (y + 1) * 16 + (xx + 1)] = g_u2[(size_t)(b0 + img) * 6272 + r];
    }
    __syncthreads();
    if (tid >= 392) return;
    int img = tid / 196, q = tid % 196;
    int oy = q / 7, t = q % 7;
    int mm = 2 * t;
    int c = (oy + 1) & 1;
    int r0 = ((oy + 1 - c) >> 1) + 1;
    float b0v = bias[0];
    u64 p1 = pk2(b0v, b0v), p2 = pk2(0.f, 0.f);
    for (int ic = 0; ic < 32; ic++) {
        const float* xs = in_s + (img * 32 + ic) * 256;
        const float* row0 = xs + r0 * 16 + mm;
        const float* row1 = row0 - 16;
        float i00 = row0[0], i01 = row0[1], i02 = row0[2], i03 = row0[3];
        float i10 = row1[0], i11 = row1[1], i12 = row1[2], i13 = row1[3];
        u64 q01a = pk2(i00, i01), q12a = pk2(i01, i02), q23a = pk2(i02, i03);
        u64 q01b = pk2(i10, i11), q12b = pk2(i11, i12), q23b = pk2(i12, i13);
        ulonglong2 wa = *(const ulonglong2*)&wpk[(c * 32 + ic) * 2];
        ulonglong2 wb = *(const ulonglong2*)&wpk[((c + 2) * 32 + ic) * 2];
        fm2(p1, q12a, wa.x); fm2(p1, q01a, wa.y);
        fm2(p2, q23a, wa.x); fm2(p2, q12a, wa.y);
        fm2(p1, q12b, wb.x); fm2(p1, q01b, wb.y);
        fm2(p2, q23b, wb.x); fm2(p2, q12b, wb.y);
    }
    float v0, v1, v2, v3;
    up2(p1, v0, v1); up2(p2, v2, v3);
    v2 += b0v; v3 += b0v;
    size_t ob = (size_t)(b0 + img) * 784 + oy * 28 + 4 * t;
    out[ob]     = 1.0f / (1.0f + expf(-v0));
    out[ob + 1] = 1.0f / (1.0f + expf(-v1));
    out[ob + 2] = 1.0f / (1.0f + expf(-v2));
    out[ob + 3] = 1.0f / (1.0f + expf(-v3));
}

// ---------------- launch ----------------
extern "C" void kernel_launch(void* const* d_in, const int* in_sizes, int n_in,
                              void* d_out, int out_size) {
    const float* x     = (const float*)d_in[0];
    const float* eps   = (const float*)d_in[1];
    const float* w_c1  = (const float*)d_in[2];
    const float* b_c1  = (const float*)d_in[3];
    const float* w_c2  = (const float*)d_in[4];
    const float* b_c2  = (const float*)d_in[5];
    const float* w_c3  = (const float*)d_in[6];
    const float* b_c3  = (const float*)d_in[7];
    const float* w_fc1 = (const float*)d_in[8];
    const float* b_fc1 = (const float*)d_in[9];
    const float* w_mu  = (const float*)d_in[10];
    const float* b_mu  = (const float*)d_in[11];
    const float* w_ls  = (const float*)d_in[12];
    const float* b_ls  = (const float*)d_in[13];
    const float* w_fc2 = (const float*)d_in[14];
    const float* b_fc2 = (const float*)d_in[15];
    const float* w_fc3 = (const float*)d_in[16];
    const float* b_fc3 = (const float*)d_in[17];
    const float* w_d1  = (const float*)d_in[18];
    const float* b_d1  = (const float*)d_in[19];
    const float* w_d2  = (const float*)d_in[20];
    const float* b_d2  = (const float*)d_in[21];
    const float* w_d3  = (const float*)d_in[22];
    const float* b_d3  = (const float*)d_in[23];
    float* out = (float*)d_out;

    cudaFuncSetAttribute(conv2_k,   cudaFuncAttributeMaxDynamicSharedMemorySize, 221184);
    cudaFuncSetAttribute(conv3_k,   cudaFuncAttributeMaxDynamicSharedMemorySize, 207360);
    cudaFuncSetAttribute(deconv1_k, cudaFuncAttributeMaxDynamicSharedMemorySize, 103424);
    cudaFuncSetAttribute(deconv2_k, cudaFuncAttributeMaxDynamicSharedMemorySize, 95232);
    cudaFuncSetAttribute(deconv3_k, cudaFuncAttributeMaxDynamicSharedMemorySize, 69632);

    float *p_h3, *p_hf, *p_f2, *p_f3;
    cudaGetSymbolAddress((void**)&p_h3, g_h3);
    cudaGetSymbolAddress((void**)&p_hf, g_hf);
    cudaGetSymbolAddress((void**)&p_f2, g_f2);
    cudaGetSymbolAddress((void**)&p_f3, g_f3);

    conv1_k<<<NB, 256, (784 + 512) * 4>>>(x, w_c1, b_c1);
    conv2_k<<<NB / 4, 800, 221184>>>(w_c2, b_c2);
    conv3_k<<<(NB + 11) / 12, 768, 207360>>>(w_c3, b_c3);
    gemm_k<<<dim3(256 / 64, NB / 32), 256>>>(p_h3, w_fc1, b_fc1, p_hf, NB, 256, 1024, 1);
    latent_k<<<(NB * 20 + 255) / 256, 256>>>(w_mu, b_mu, w_ls, b_ls, eps, out);
    fc2_k<<<(NB * 256 + 255) / 256, 256>>>(w_fc2, b_fc2);
    gemm_k<<<dim3(1024 / 64, NB / 32), 256>>>(p_f2, w_fc3, b_fc3, p_f3, NB, 1024, 256, 1);
    deconv1_k<<<(NB + 4) / 5, 992, 103424>>>(w_d1, b_d1);
    deconv2_k<<<NB / 2, 800, 95232>>>(w_d2, b_d2);
    deconv3_k<<<NB / 2, 416, 69632>>>(w_d3, b_d3, out);
}

// round 9
// speedup vs baseline: 1.2293x; 1.2293x over previous
#include <cuda_runtime.h>
#include <math.h>

#define NB 4096
typedef unsigned long long u64;

__device__ __forceinline__ u64 pk2(float lo, float hi) {
    u64 r; asm("mov.b64 %0,{%1,%2};" : "=l"(r) : "f"(lo), "f"(hi)); return r;
}
__device__ __forceinline__ u64 dup2(float x) { return pk2(x, x); }
__device__ __forceinline__ void fm2(u64& d, u64 a, u64 b) {
    asm("fma.rn.f32x2 %0,%1,%2,%0;" : "+l"(d) : "l"(a), "l"(b));
}
__device__ __forceinline__ void up2(u64 v, float& a, float& b) {
    asm("mov.b64 {%0,%1},%2;" : "=f"(a), "=f"(b) : "l"(v));
}

// ---------------- scratch ----------------
__device__ float g_h1[NB * 32 * 196];
__device__ float g_h2[NB * 32 * 49];
__device__ float g_h3[NB * 1024];
__device__ float g_hf[NB * 256];
__device__ float g_z [NB * 20];
__device__ float g_f2[NB * 256];
__device__ float g_f3[NB * 1024];
__device__ float g_u1[NB * 32 * 49];
__device__ float g_u2[NB * 32 * 196];

#define MU_OFF   (NB * 784)
#define LS_OFF   (NB * 784 + NB * 20)

// ---------------- conv1 (R5) ----------------
__global__ void conv1_k(const float* __restrict__ x, const float* __restrict__ w,
                        const float* __restrict__ bias) {
    extern __shared__ float sm[];
    float* in_s = sm;          // 784
    float* w_s  = sm + 784;    // 512, [kk][oc]
    int b = blockIdx.x, tid = threadIdx.x;
    const float* xin = x + b * 784;
    for (int i = tid; i < 784; i += 256) in_s[i] = xin[i];
    for (int i = tid; i < 512; i += 256) { int oc = i & 31, kk = i >> 5; w_s[kk * 32 + oc] = w[oc * 16 + kk]; }
    __syncthreads();
    for (int u = tid; u < 784; u += 256) {
        int p = u >> 2, g = u & 3;
        int oy = p / 14, ox = p % 14;
        u64 acc[4];
        #pragma unroll
        for (int j = 0; j < 4; j++) acc[j] = pk2(bias[g * 8 + 2 * j], bias[g * 8 + 2 * j + 1]);
        #pragma unroll
        for (int ky = 0; ky < 4; ky++) {
            int iy = oy * 2 - 1 + ky;
            if (iy < 0 || iy >= 28) continue;
            #pragma unroll
            for (int kx = 0; kx < 4; kx++) {
                int ix = ox * 2 - 1 + kx;
                if (ix < 0 || ix >= 28) continue;
                u64 xd = dup2(in_s[iy * 28 + ix]);
                const ulonglong2* wq = (const ulonglong2*)(w_s + (ky * 4 + kx) * 32 + g * 8);
                ulonglong2 w0 = wq[0];
                fm2(acc[0], xd, w0.x); fm2(acc[1], xd, w0.y);
                ulonglong2 w1 = wq[1];
                fm2(acc[2], xd, w1.x); fm2(acc[3], xd, w1.y);
            }
        }
        #pragma unroll
        for (int j = 0; j < 4; j++) {
            float lo, hi; up2(acc[j], lo, hi);
            g_h1[(size_t)(b * 32 + g * 8 + 2 * j)     * 196 + p] = fmaxf(lo, 0.f);
            g_h1[(size_t)(b * 32 + g * 8 + 2 * j + 1) * 196 + p] = fmaxf(hi, 0.f);
        }
    }
}

// ---------------- conv2: 4 img/block, thread = (img, pixel-pair, quarter:8oc) ----------------
// weights reused across 2 pixels: 4 smem wavefronts per 8 FFMA2 per tap
__global__ void conv2_k(const float* __restrict__ w, const float* __restrict__ bias) {
    extern __shared__ float sm[];
    float* in_s = sm;            // 4*32*288 = 36864
    float* w_s  = sm + 36864;    // 512*36, [ic*16+kk][oc]
    int b0 = blockIdx.x * 4, tid = threadIdx.x, nt = blockDim.x;
    float4* z4 = (float4*)in_s;
    for (int i = tid; i < 9216; i += nt) z4[i] = make_float4(0.f, 0.f, 0.f, 0.f);
    for (int i = tid; i < 16384; i += nt) {
        int oc = i & 31, rest = i >> 5;
        w_s[rest * 36 + oc] = w[oc * 512 + rest];
    }
    __syncthreads();
    for (int i = tid; i < 4 * 6272; i += nt) {
        int img = i / 6272, r = i % 6272;
        int ic = r / 196, q = r % 196, y = q / 14, xx = q % 14;
        in_s[(img * 32 + ic) * 288 + (y + 1) * 18 + (xx + 1)] = g_h1[(size_t)(b0 + img) * 6272 + r];
    }
    __syncthreads();
    if (tid >= 400) return;
    int img = tid / 100, rr = tid % 100;
    int pp = rr % 25, q = rr / 25;        // q: 8-oc quarter
    int pA = pp, pB = pp + 25;
    int validB = (pB < 49);
    int pBc = validB ? pB : 24;
    int oyA = pA / 7, oxA = pA % 7;
    int oyB = pBc / 7, oxB = pBc % 7;
    u64 accA[4], accB[4];
    #pragma unroll
    for (int j = 0; j < 4; j++) {
        u64 bv = pk2(bias[q * 8 + 2 * j], bias[q * 8 + 2 * j + 1]);
        accA[j] = bv; accB[j] = bv;
    }
    for (int ic = 0; ic < 32; ic++) {
        const float* base = in_s + (img * 32 + ic) * 288;
        const float* xsA = base + (oyA * 2) * 18 + oxA * 2;
        const float* xsB = base + (oyB * 2) * 18 + oxB * 2;
        const float* wb = w_s + (ic * 16) * 36 + q * 8;
        #pragma unroll
        for (int kk = 0; kk < 16; kk++) {
            u64 xdA = dup2(xsA[(kk >> 2) * 18 + (kk & 3)]);
            u64 xdB = dup2(xsB[(kk >> 2) * 18 + (kk & 3)]);
            const ulonglong2* wq = (const ulonglong2*)(wb + kk * 36);
            ulonglong2 w0 = wq[0], w1 = wq[1];
            fm2(accA[0], xdA, w0.x); fm2(accA[1], xdA, w0.y);
            fm2(accA[2], xdA, w1.x); fm2(accA[3], xdA, w1.y);
            fm2(accB[0], xdB, w0.x); fm2(accB[1], xdB, w0.y);
            fm2(accB[2], xdB, w1.x); fm2(accB[3], xdB, w1.y);
        }
    }
    #pragma unroll
    for (int j = 0; j < 4; j++) {
        float lo, hi; up2(accA[j], lo, hi);
        g_h2[(size_t)((b0 + img) * 32 + q * 8 + 2 * j)     * 49 + pA] = fmaxf(lo, 0.f);
        g_h2[(size_t)((b0 + img) * 32 + q * 8 + 2 * j + 1) * 49 + pA] = fmaxf(hi, 0.f);
    }
    if (validB) {
        #pragma unroll
        for (int j = 0; j < 4; j++) {
            float lo, hi; up2(accB[j], lo, hi);
            g_h2[(size_t)((b0 + img) * 32 + q * 8 + 2 * j)     * 49 + pB] = fmaxf(lo, 0.f);
            g_h2[(size_t)((b0 + img) * 32 + q * 8 + 2 * j + 1) * 49 + pB] = fmaxf(hi, 0.f);
        }
    }
}

// ---------------- conv3 (R5): 12 img/block, 384 threads, acc 32 oc ----------------
__global__ void conv3_k(const float* __restrict__ w, const float* __restrict__ bias) {
    extern __shared__ float sm[];
    float* in_s = sm;            // 12*32*84 = 32256
    float* w_s  = sm + 32256;    // 288*68, [ic*9+kk][oc]
    int b0 = blockIdx.x * 12, tid = threadIdx.x, nt = blockDim.x;
    int nimg = min(12, NB - b0);
    float4* z4 = (float4*)in_s;
    for (int i = tid; i < 8064; i += nt) z4[i] = make_float4(0.f, 0.f, 0.f, 0.f);
    for (int i = tid; i < 18432; i += nt) {
        int oc = i & 63, rest = i >> 6;
        w_s[rest * 68 + oc] = w[oc * 288 + rest];
    }
    __syncthreads();
    for (int i = tid; i < nimg * 1568; i += nt) {
        int img = i / 1568, r = i % 1568;
        int ic = r / 49, q = r % 49, y = q / 7, xx = q % 7;
        in_s[(img * 32 + ic) * 84 + (y + 1) * 9 + (xx + 1)] = g_h2[(size_t)(b0 + img) * 1568 + r];
    }
    __syncthreads();
    int img = tid / 32, rr = tid % 32;
    if (img >= nimg) return;
    int p = rr & 15, half = rr >> 4;
    int oy = p >> 2, ox = p & 3;
    u64 acc[16];
    #pragma unroll
    for (int j = 0; j < 16; j++) acc[j] = pk2(bias[half * 32 + 2 * j], bias[half * 32 + 2 * j + 1]);
    for (int ic = 0; ic < 32; ic++) {
        const float* xs = in_s + (img * 32 + ic) * 84 + (oy * 2) * 9 + ox * 2;
        const float* wb = w_s + (ic * 9) * 68 + half * 32;
        #pragma unroll
        for (int kk = 0; kk < 9; kk++) {
            u64 xd = dup2(xs[(kk / 3) * 9 + (kk % 3)]);
            const ulonglong2* wq = (const ulonglong2*)(wb + kk * 68);
            #pragma unroll
            for (int v = 0; v < 8; v++) {
                ulonglong2 wv = wq[v];
                fm2(acc[2 * v], xd, wv.x); fm2(acc[2 * v + 1], xd, wv.y);
            }
        }
    }
    #pragma unroll
    for (int j = 0; j < 16; j++) {
        float lo, hi; up2(acc[j], lo, hi);
        g_h3[(size_t)((b0 + img) * 64 + half * 32 + 2 * j)     * 16 + p] = fmaxf(lo, 0.f);
        g_h3[(size_t)((b0 + img) * 64 + half * 32 + 2 * j + 1) * 16 + p] = fmaxf(hi, 0.f);
    }
}

// ---------------- NT GEMM: BM=64, BN=64, BK=16, 128 threads, 4x8 register tile ----------------
__global__ void gemm_k(const float* __restrict__ A, const float* __restrict__ W,
                       const float* __restrict__ bias, float* __restrict__ C,
                       int M, int N, int K, int relu) {
    __shared__ float As[16 * 68];
    __shared__ float Ws[16 * 68];
    int tid = threadIdx.x, tx = tid & 7, ty = tid >> 3;   // tx 0..7 (n), ty 0..15 (m)
    int m0 = blockIdx.y * 64, n0 = blockIdx.x * 64;
    u64 acc[4][4] = {};
    for (int kt = 0; kt < K; kt += 16) {
        #pragma unroll
        for (int i = 0; i < 8; i++) {
            int idx = tid + i * 128;
            int k = idx & 15, m = idx >> 4;
            As[k * 68 + m] = A[(size_t)(m0 + m) * K + kt + k];
        }
        #pragma unroll
        for (int i = 0; i < 8; i++) {
            int idx = tid + i * 128;
            int k = idx & 15, n = idx >> 4;
            Ws[k * 68 + n] = W[(size_t)(n0 + n) * K + kt + k];
        }
        __syncthreads();
        #pragma unroll
        for (int kk = 0; kk < 16; kk++) {
            float4 a = *(const float4*)&As[kk * 68 + ty * 4];
            const ulonglong2* wp = (const ulonglong2*)&Ws[kk * 68 + tx * 8];
            ulonglong2 b0 = wp[0], b1 = wp[1];
            u64 av[4] = {dup2(a.x), dup2(a.y), dup2(a.z), dup2(a.w)};
            #pragma unroll
            for (int i = 0; i < 4; i++) {
                fm2(acc[i][0], av[i], b0.x); fm2(acc[i][1], av[i], b0.y);
                fm2(acc[i][2], av[i], b1.x); fm2(acc[i][3], av[i], b1.y);
            }
        }
        __syncthreads();
    }
    #pragma unroll
    for (int i = 0; i < 4; i++) {
        int m = m0 + ty * 4 + i;
        #pragma unroll
        for (int j = 0; j < 4; j++) {
            float lo, hi; up2(acc[i][j], lo, hi);
            int n = n0 + tx * 8 + 2 * j;
            float v0 = lo + bias[n], v1 = hi + bias[n + 1];
            if (relu) { v0 = fmaxf(v0, 0.f); v1 = fmaxf(v1, 0.f); }
            C[(size_t)m * N + n] = v0;
            C[(size_t)m * N + n + 1] = v1;
        }
    }
}

// ---------------- latent ----------------
__global__ void latent_k(const float* __restrict__ w_mu, const float* __restrict__ b_mu,
                         const float* __restrict__ w_ls, const float* __restrict__ b_ls,
                         const float* __restrict__ eps, float* __restrict__ out) {
    int idx = blockIdx.x * 256 + threadIdx.x;
    if (idx >= NB * 20) return;
    int b = idx / 20, l = idx % 20;
    const float4* h4 = (const float4*)(g_hf + (size_t)b * 256);
    const float4* wm = (const float4*)(w_mu + (size_t)l * 256);
    const float4* wl = (const float4*)(w_ls + (size_t)l * 256);
    float sm_ = 0.f, sl_ = 0.f;
    #pragma unroll 8
    for (int k = 0; k < 64; k++) {
        float4 h = h4[k], a = wm[k], c = wl[k];
        sm_ += h.x * a.x + h.y * a.y + h.z * a.z + h.w * a.w;
        sl_ += h.x * c.x + h.y * c.y + h.z * c.z + h.w * c.w;
    }
    float mu = sm_ + b_mu[l];
    float ls = sl_ + b_ls[l];
    out[MU_OFF + idx] = mu;
    out[LS_OFF + idx] = ls;
    float m = mu, s = ls;
    #pragma unroll 4
    for (int i = 0; i < 100; i++) {
        m = m + 0.1f * m;
        s = s + 0.05f * (expf(s) - 1.0f);
    }
    g_z[idx] = eps[idx] * expf(0.5f * s) + m;
}

// ---------------- fc2 ----------------
__global__ void fc2_k(const float* __restrict__ w, const float* __restrict__ bias) {
    int idx = blockIdx.x * 256 + threadIdx.x;
    if (idx >= NB * 256) return;
    int b = idx >> 8, o = idx & 255;
    const float* z = g_z + (size_t)b * 20;
    const float* wr = w + (size_t)o * 20;
    float acc = bias[o];
    #pragma unroll
    for (int k = 0; k < 20; k++) acc += z[k] * wr[k];
    g_f2[idx] = fmaxf(acc, 0.f);
}

// ---------------- deconv1: 6 img/block, thread = (image-pair, p, half:16oc) ----------------
__global__ void deconv1_k(const float* __restrict__ w, const float* __restrict__ bias) {
    extern __shared__ float sm[];
    float* in_s = sm;            // 6*1024 = 6144
    float* w_s  = sm + 6144;     // 576*36 = 20736, [ic*9+kk][oc]
    int b0 = blockIdx.x * 6, tid = threadIdx.x, nt = blockDim.x;
    int nimg = min(6, NB - b0);
    for (int i = tid; i < nimg * 1024; i += nt) in_s[i] = g_f3[(size_t)b0 * 1024 + i];
    for (int i = tid; i < 18432; i += nt) {
        int oc = i & 31, rest = i >> 5;
        int ic = rest / 9, kk = rest % 9;
        w_s[rest * 36 + oc] = w[ic * 288 + oc * 9 + kk];
    }
    __syncthreads();
    if (tid >= 294) return;
    int ip = tid / 98, rr = tid % 98;
    int p = rr % 49, half = rr / 49;
    int imgA = 2 * ip, imgB = 2 * ip + 1;
    int vA = imgA < nimg, vB = imgB < nimg;
    if (!vA) return;
    int imgBc = vB ? imgB : imgA;
    int oy = p / 7, ox = p % 7;
    int kyA = (oy & 1) ? 0 : 1;
    int iyA = (oy + 1 - kyA) >> 1;
    int vyB = oy & 1;
    int iyB = (oy >= 1) ? ((oy - 1) >> 1) : 0;
    int kxA = (ox & 1) ? 0 : 1;
    int ixA = (ox + 1 - kxA) >> 1;
    int vxB = ox & 1;
    int ixB = (ox >= 1) ? ((ox - 1) >> 1) : 0;
    int kyT[2] = {kyA, 2}, iyT[2] = {iyA, iyB};
    int kxT[2] = {kxA, 2}, ixT[2] = {ixA, ixB};
    int vy[2] = {1, vyB}, vx[2] = {1, vxB};
    u64 accA[8], accB[8];
    #pragma unroll
    for (int j = 0; j < 8; j++) {
        u64 bv = pk2(bias[half * 16 + 2 * j], bias[half * 16 + 2 * j + 1]);
        accA[j] = bv; accB[j] = bv;
    }
    for (int ic = 0; ic < 64; ic++) {
        const float* xsA = in_s + imgA * 1024 + ic * 16;
        const float* xsB = in_s + imgBc * 1024 + ic * 16;
        #pragma unroll
        for (int a = 0; a < 2; a++) {
            #pragma unroll
            for (int bb = 0; bb < 2; bb++) {
                int valid = vy[a] & vx[bb];
                int off = iyT[a] * 4 + ixT[bb];
                u64 xdA = dup2(valid ? xsA[off] : 0.f);
                u64 xdB = dup2(valid ? xsB[off] : 0.f);
                const ulonglong2* wq = (const ulonglong2*)(w_s + (ic * 9 + kyT[a] * 3 + kxT[bb]) * 36 + half * 16);
                ulonglong2 w0 = wq[0], w1 = wq[1], w2 = wq[2], w3 = wq[3];
                fm2(accA[0], xdA, w0.x); fm2(accA[1], xdA, w0.y);
                fm2(accA[2], xdA, w1.x); fm2(accA[3], xdA, w1.y);
                fm2(accA[4], xdA, w2.x); fm2(accA[5], xdA, w2.y);
                fm2(accA[6], xdA, w3.x); fm2(accA[7], xdA, w3.y);
                fm2(accB[0], xdB, w0.x); fm2(accB[1], xdB, w0.y);
                fm2(accB[2], xdB, w1.x); fm2(accB[3], xdB, w1.y);
                fm2(accB[4], xdB, w2.x); fm2(accB[5], xdB, w2.y);
                fm2(accB[6], xdB, w3.x); fm2(accB[7], xdB, w3.y);
            }
        }
    }
    #pragma unroll
    for (int j = 0; j < 8; j++) {
        float lo, hi; up2(accA[j], lo, hi);
        g_u1[(size_t)((b0 + imgA) * 32 + half * 16 + 2 * j)     * 49 + p] = fmaxf(lo, 0.f);
        g_u1[(size_t)((b0 + imgA) * 32 + half * 16 + 2 * j + 1) * 49 + p] = fmaxf(hi, 0.f);
    }
    if (vB) {
        #pragma unroll
        for (int j = 0; j < 8; j++) {
            float lo, hi; up2(accB[j], lo, hi);
            g_u1[(size_t)((b0 + imgB) * 32 + half * 16 + 2 * j)     * 49 + p] = fmaxf(lo, 0.f);
            g_u1[(size_t)((b0 + imgB) * 32 + half * 16 + 2 * j + 1) * 49 + p] = fmaxf(hi, 0.f);
        }
    }
}

// ---------------- deconv2: 2 img/block, thread = (p, half:16oc) computing BOTH images ----------------
__global__ void deconv2_k(const float* __restrict__ w, const float* __restrict__ bias) {
    extern __shared__ float sm[];
    float* in_s = sm;            // 2*32*84 = 5376
    float* w_s  = sm + 5376;     // 512*36, [ic*16+kk][oc]
    int b0 = blockIdx.x * 2, tid = threadIdx.x, nt = blockDim.x;
    float4* z4 = (float4*)in_s;
    for (int i = tid; i < 1344; i += nt) z4[i] = make_float4(0.f, 0.f, 0.f, 0.f);
    for (int i = tid; i < 16384; i += nt) {
        int oc = i & 31, rest = i >> 5;
        w_s[rest * 36 + oc] = w[(rest >> 4) * 512 + oc * 16 + (rest & 15)];
    }
    __syncthreads();
    for (int i = tid; i < 2 * 1568; i += nt) {
        int img = i / 1568, r = i % 1568;
        int ic = r / 49, q = r % 49, y = q / 7, xx = q % 7;
        in_s[(img * 32 + ic) * 84 + (y + 1) * 9 + (xx + 1)] = g_u1[(size_t)(b0 + img) * 1568 + r];
    }
    __syncthreads();
    if (tid >= 392) return;
    int p = tid % 196, half = tid / 196;
    int oy = p / 14, ox = p % 14;
    int c = (oy + 1) & 1;
    int r0 = ((oy + 1 - c) >> 1) + 1;
    int d = (ox + 1) & 1;
    int c0 = ((ox + 1 - d) >> 1) + 1;
    u64 accA[8], accB[8];
    #pragma unroll
    for (int j = 0; j < 8; j++) {
        u64 bv = pk2(bias[half * 16 + 2 * j], bias[half * 16 + 2 * j + 1]);
        accA[j] = bv; accB[j] = bv;
    }
    for (int ic = 0; ic < 32; ic++) {
        const float* xsA = in_s + ic * 84;
        const float* xsB = in_s + (32 + ic) * 84;
        #pragma unroll
        for (int a = 0; a < 2; a++) {
            #pragma unroll
            for (int bb = 0; bb < 2; bb++) {
                int off = (r0 - a) * 9 + (c0 - bb);
                u64 xdA = dup2(xsA[off]);
                u64 xdB = dup2(xsB[off]);
                int kk = (c + 2 * a) * 4 + (d + 2 * bb);
                const ulonglong2* wq = (const ulonglong2*)(w_s + (ic * 16 + kk) * 36 + half * 16);
                ulonglong2 w0 = wq[0], w1 = wq[1], w2 = wq[2], w3 = wq[3];
                fm2(accA[0], xdA, w0.x); fm2(accA[1], xdA, w0.y);
                fm2(accA[2], xdA, w1.x); fm2(accA[3], xdA, w1.y);
                fm2(accA[4], xdA, w2.x); fm2(accA[5], xdA, w2.y);
                fm2(accA[6], xdA, w3.x); fm2(accA[7], xdA, w3.y);
                fm2(accB[0], xdB, w0.x); fm2(accB[1], xdB, w0.y);
                fm2(accB[2], xdB, w1.x); fm2(accB[3], xdB, w1.y);
                fm2(accB[4], xdB, w2.x); fm2(accB[5], xdB, w2.y);
                fm2(accB[6], xdB, w3.x); fm2(accB[7], xdB, w3.y);
            }
        }
    }
    #pragma unroll
    for (int j = 0; j < 8; j++) {
        float lo, hi; up2(accA[j], lo, hi);
        g_u2[(size_t)(b0 * 32 + half * 16 + 2 * j)     * 196 + p] = fmaxf(lo, 0.f);
        g_u2[(size_t)(b0 * 32 + half * 16 + 2 * j + 1) * 196 + p] = fmaxf(hi, 0.f);
    }
    #pragma unroll
    for (int j = 0; j < 8; j++) {
        float lo, hi; up2(accB[j], lo, hi);
        g_u2[(size_t)((b0 + 1) * 32 + half * 16 + 2 * j)     * 196 + p] = fmaxf(lo, 0.f);
        g_u2[(size_t)((b0 + 1) * 32 + half * 16 + 2 * j + 1) * 196 + p] = fmaxf(hi, 0.f);
    }
}

// ---------------- deconv3 (R5) ----------------
__global__ void deconv3_k(const float* __restrict__ w, const float* __restrict__ bias,
                          float* __restrict__ out) {
    extern __shared__ float sm[];
    float* in_s = sm;                    // 2*32*256 = 16384
    u64*   wpk  = (u64*)(sm + 16384);    // 256 u64
    int b0 = blockIdx.x * 2, tid = threadIdx.x, nt = blockDim.x;
    float4* z4 = (float4*)in_s;
    for (int i = tid; i < 4096; i += nt) z4[i] = make_float4(0.f, 0.f, 0.f, 0.f);
    for (int i = tid; i < 256; i += nt) {
        int t = i & 1, rest = i >> 1;
        int ic = rest & 31, ky = rest >> 5;
        wpk[(ky * 32 + ic) * 2 + t] = pk2(w[ic * 16 + ky * 4 + 2 * t + 1], w[ic * 16 + ky * 4 + 2 * t]);
    }
    __syncthreads();
    for (int i = tid; i < 2 * 6272; i += nt) {
        int img = i / 6272, r = i % 6272;
        int ic = r / 196, q = r % 196, y = q / 14, xx = q % 14;
        in_s[(img * 32 + ic) * 256 + (y + 1) * 16 + (xx + 1)] = g_u2[(size_t)(b0 + img) * 6272 + r];
    }
    __syncthreads();
    if (tid >= 392) return;
    int img = tid / 196, q = tid % 196;
    int oy = q / 7, t = q % 7;
    int mm = 2 * t;
    int c = (oy + 1) & 1;
    int r0 = ((oy + 1 - c) >> 1) + 1;
    float b0v = bias[0];
    u64 p1 = pk2(b0v, b0v), p2 = pk2(0.f, 0.f);
    for (int ic = 0; ic < 32; ic++) {
        const float* xs = in_s + (img * 32 + ic) * 256;
        const float* row0 = xs + r0 * 16 + mm;
        const float* row1 = row0 - 16;
        float i00 = row0[0], i01 = row0[1], i02 = row0[2], i03 = row0[3];
        float i10 = row1[0], i11 = row1[1], i12 = row1[2], i13 = row1[3];
        u64 q01a = pk2(i00, i01), q12a = pk2(i01, i02), q23a = pk2(i02, i03);
        u64 q01b = pk2(i10, i11), q12b = pk2(i11, i12), q23b = pk2(i12, i13);
        ulonglong2 wa = *(const ulonglong2*)&wpk[(c * 32 + ic) * 2];
        ulonglong2 wb = *(const ulonglong2*)&wpk[((c + 2) * 32 + ic) * 2];
        fm2(p1, q12a, wa.x); fm2(p1, q01a, wa.y);
        fm2(p2, q23a, wa.x); fm2(p2, q12a, wa.y);
        fm2(p1, q12b, wb.x); fm2(p1, q01b, wb.y);
        fm2(p2, q23b, wb.x); fm2(p2, q12b, wb.y);
    }
    float v0, v1, v2, v3;
    up2(p1, v0, v1); up2(p2, v2, v3);
    v2 += b0v; v3 += b0v;
    size_t ob = (size_t)(b0 + img) * 784 + oy * 28 + 4 * t;
    out[ob]     = 1.0f / (1.0f + expf(-v0));
    out[ob + 1] = 1.0f / (1.0f + expf(-v1));
    out[ob + 2] = 1.0f / (1.0f + expf(-v2));
    out[ob + 3] = 1.0f / (1.0f + expf(-v3));
}

// ---------------- launch ----------------
extern "C" void kernel_launch(void* const* d_in, const int* in_sizes, int n_in,
                              void* d_out, int out_size) {
    const float* x     = (const float*)d_in[0];
    const float* eps   = (const float*)d_in[1];
    const float* w_c1  = (const float*)d_in[2];
    const float* b_c1  = (const float*)d_in[3];
    const float* w_c2  = (const float*)d_in[4];
    const float* b_c2  = (const float*)d_in[5];
    const float* w_c3  = (const float*)d_in[6];
    const float* b_c3  = (const float*)d_in[7];
    const float* w_fc1 = (const float*)d_in[8];
    const float* b_fc1 = (const float*)d_in[9];
    const float* w_mu  = (const float*)d_in[10];
    const float* b_mu  = (const float*)d_in[11];
    const float* w_ls  = (const float*)d_in[12];
    const float* b_ls  = (const float*)d_in[13];
    const float* w_fc2 = (const float*)d_in[14];
    const float* b_fc2 = (const float*)d_in[15];
    const float* w_fc3 = (const float*)d_in[16];
    const float* b_fc3 = (const float*)d_in[17];
    const float* w_d1  = (const float*)d_in[18];
    const float* b_d1  = (const float*)d_in[19];
    const float* w_d2  = (const float*)d_in[20];
    const float* b_d2  = (const float*)d_in[21];
    const float* w_d3  = (const float*)d_in[22];
    const float* b_d3  = (const float*)d_in[23];
    float* out = (float*)d_out;

    cudaFuncSetAttribute(conv2_k,   cudaFuncAttributeMaxDynamicSharedMemorySize, 221184);
    cudaFuncSetAttribute(conv3_k,   cudaFuncAttributeMaxDynamicSharedMemorySize, 207360);
    cudaFuncSetAttribute(deconv1_k, cudaFuncAttributeMaxDynamicSharedMemorySize, 107520);
    cudaFuncSetAttribute(deconv2_k, cudaFuncAttributeMaxDynamicSharedMemorySize, 95232);
    cudaFuncSetAttribute(deconv3_k, cudaFuncAttributeMaxDynamicSharedMemorySize, 69632);

    float *p_h3, *p_hf, *p_f2, *p_f3;
    cudaGetSymbolAddress((void**)&p_h3, g_h3);
    cudaGetSymbolAddress((void**)&p_hf, g_hf);
    cudaGetSymbolAddress((void**)&p_f2, g_f2);
    cudaGetSymbolAddress((void**)&p_f3, g_f3);

    conv1_k<<<NB, 256, (784 + 512) * 4>>>(x, w_c1, b_c1);
    conv2_k<<<NB / 4, 416, 221184>>>(w_c2, b_c2);
    conv3_k<<<(NB + 11) / 12, 384, 207360>>>(w_c3, b_c3);
    gemm_k<<<dim3(256 / 64, NB / 64), 128>>>(p_h3, w_fc1, b_fc1, p_hf, NB, 256, 1024, 1);
    latent_k<<<(NB * 20 + 255) / 256, 256>>>(w_mu, b_mu, w_ls, b_ls, eps, out);
    fc2_k<<<(NB * 256 + 255) / 256, 256>>>(w_fc2, b_fc2);
    gemm_k<<<dim3(1024 / 64, NB / 64), 128>>>(p_f2, w_fc3, b_fc3, p_f3, NB, 1024, 256, 1);
    deconv1_k<<<(NB + 5) / 6, 320, 107520>>>(w_d1, b_d1);
    deconv2_k<<<NB / 2, 416, 95232>>>(w_d2, b_d2);
    deconv3_k<<<NB / 2, 416, 69632>>>(w_d3, b_d3, out);
}

// round 11
// speedup vs baseline: 1.3189x; 1.0729x over previous
#include <cuda_runtime.h>
#include <math.h>

#define NB 4096
typedef unsigned long long u64;

__device__ __forceinline__ u64 pk2(float lo, float hi) {
    u64 r; asm("mov.b64 %0,{%1,%2};" : "=l"(r) : "f"(lo), "f"(hi)); return r;
}
__device__ __forceinline__ u64 dup2(float x) { return pk2(x, x); }
__device__ __forceinline__ void fm2(u64& d, u64 a, u64 b) {
    asm("fma.rn.f32x2 %0,%1,%2,%0;" : "+l"(d) : "l"(a), "l"(b));
}
__device__ __forceinline__ void up2(u64 v, float& a, float& b) {
    asm("mov.b64 {%0,%1},%2;" : "=f"(a), "=f"(b) : "l"(v));
}

// ---------------- scratch ----------------
__device__ float g_h1[NB * 32 * 196];
__device__ float g_h2[NB * 32 * 49];
__device__ float g_h3[NB * 1024];
__device__ float g_hf[NB * 256];
__device__ float g_z [NB * 20];
__device__ float g_f2[NB * 256];
__device__ float g_f3[NB * 1024];
__device__ float g_u1[NB * 32 * 49];
__device__ float g_u2[NB * 32 * 196];

#define MU_OFF   (NB * 784)
#define LS_OFF   (NB * 784 + NB * 20)

// ---------------- conv1 ----------------
__global__ void conv1_k(const float* __restrict__ x, const float* __restrict__ w,
                        const float* __restrict__ bias) {
    extern __shared__ float sm[];
    float* in_s = sm;          // 784
    float* w_s  = sm + 784;    // 512, [kk][oc]
    int b = blockIdx.x, tid = threadIdx.x;
    const float* xin = x + b * 784;
    for (int i = tid; i < 784; i += 256) in_s[i] = xin[i];
    for (int i = tid; i < 512; i += 256) { int oc = i & 31, kk = i >> 5; w_s[kk * 32 + oc] = w[oc * 16 + kk]; }
    __syncthreads();
    for (int u = tid; u < 784; u += 256) {
        int p = u >> 2, g = u & 3;
        int oy = p / 14, ox = p % 14;
        u64 acc[4];
        #pragma unroll
        for (int j = 0; j < 4; j++) acc[j] = pk2(bias[g * 8 + 2 * j], bias[g * 8 + 2 * j + 1]);
        #pragma unroll
        for (int ky = 0; ky < 4; ky++) {
            int iy = oy * 2 - 1 + ky;
            if (iy < 0 || iy >= 28) continue;
            #pragma unroll
            for (int kx = 0; kx < 4; kx++) {
                int ix = ox * 2 - 1 + kx;
                if (ix < 0 || ix >= 28) continue;
                u64 xd = dup2(in_s[iy * 28 + ix]);
                const ulonglong2* wq = (const ulonglong2*)(w_s + (ky * 4 + kx) * 32 + g * 8);
                ulonglong2 w0 = wq[0];
                fm2(acc[0], xd, w0.x); fm2(acc[1], xd, w0.y);
                ulonglong2 w1 = wq[1];
                fm2(acc[2], xd, w1.x); fm2(acc[3], xd, w1.y);
            }
        }
        #pragma unroll
        for (int j = 0; j < 4; j++) {
            float lo, hi; up2(acc[j], lo, hi);
            g_h1[(size_t)(b * 32 + g * 8 + 2 * j)     * 196 + p] = fmaxf(lo, 0.f);
            g_h1[(size_t)(b * 32 + g * 8 + 2 * j + 1) * 196 + p] = fmaxf(hi, 0.f);
        }
    }
}

// ---------------- conv2: 4 img/block, thread = (img, pixel-pair, quarter:8oc) ----------------
__global__ void conv2_k(const float* __restrict__ w, const float* __restrict__ bias) {
    extern __shared__ float sm[];
    float* in_s = sm;            // 4*32*288 = 36864
    float* w_s  = sm + 36864;    // 512*36, [ic*16+kk][oc]
    int b0 = blockIdx.x * 4, tid = threadIdx.x, nt = blockDim.x;
    float4* z4 = (float4*)in_s;
    for (int i = tid; i < 9216; i += nt) z4[i] = make_float4(0.f, 0.f, 0.f, 0.f);
    for (int i = tid; i < 16384; i += nt) {
        int oc = i & 31, rest = i >> 5;
        w_s[rest * 36 + oc] = w[oc * 512 + rest];
    }
    __syncthreads();
    for (int i = tid; i < 4 * 6272; i += nt) {
        int img = i / 6272, r = i % 6272;
        int ic = r / 196, q = r % 196, y = q / 14, xx = q % 14;
        in_s[(img * 32 + ic) * 288 + (y + 1) * 18 + (xx + 1)] = g_h1[(size_t)(b0 + img) * 6272 + r];
    }
    __syncthreads();
    if (tid >= 400) return;
    int img = tid / 100, rr = tid % 100;
    int pp = rr % 25, q = rr / 25;
    int pA = pp, pB = pp + 25;
    int validB = (pB < 49);
    int pBc = validB ? pB : 24;
    int oyA = pA / 7, oxA = pA % 7;
    int oyB = pBc / 7, oxB = pBc % 7;
    u64 accA[4], accB[4];
    #pragma unroll
    for (int j = 0; j < 4; j++) {
        u64 bv = pk2(bias[q * 8 + 2 * j], bias[q * 8 + 2 * j + 1]);
        accA[j] = bv; accB[j] = bv;
    }
    for (int ic = 0; ic < 32; ic++) {
        const float* base = in_s + (img * 32 + ic) * 288;
        const float* xsA = base + (oyA * 2) * 18 + oxA * 2;
        const float* xsB = base + (oyB * 2) * 18 + oxB * 2;
        const float* wb = w_s + (ic * 16) * 36 + q * 8;
        #pragma unroll
        for (int kk = 0; kk < 16; kk++) {
            u64 xdA = dup2(xsA[(kk >> 2) * 18 + (kk & 3)]);
            u64 xdB = dup2(xsB[(kk >> 2) * 18 + (kk & 3)]);
            const ulonglong2* wq = (const ulonglong2*)(wb + kk * 36);
            ulonglong2 w0 = wq[0], w1 = wq[1];
            fm2(accA[0], xdA, w0.x); fm2(accA[1], xdA, w0.y);
            fm2(accA[2], xdA, w1.x); fm2(accA[3], xdA, w1.y);
            fm2(accB[0], xdB, w0.x); fm2(accB[1], xdB, w0.y);
            fm2(accB[2], xdB, w1.x); fm2(accB[3], xdB, w1.y);
        }
    }
    #pragma unroll
    for (int j = 0; j < 4; j++) {
        float lo, hi; up2(accA[j], lo, hi);
        g_h2[(size_t)((b0 + img) * 32 + q * 8 + 2 * j)     * 49 + pA] = fmaxf(lo, 0.f);
        g_h2[(size_t)((b0 + img) * 32 + q * 8 + 2 * j + 1) * 49 + pA] = fmaxf(hi, 0.f);
    }
    if (validB) {
        #pragma unroll
        for (int j = 0; j < 4; j++) {
            float lo, hi; up2(accB[j], lo, hi);
            g_h2[(size_t)((b0 + img) * 32 + q * 8 + 2 * j)     * 49 + pB] = fmaxf(lo, 0.f);
            g_h2[(size_t)((b0 + img) * 32 + q * 8 + 2 * j + 1) * 49 + pB] = fmaxf(hi, 0.f);
        }
    }
}

// ---------------- conv3: 12 img/block, 384 threads, acc 32 oc ----------------
__global__ void conv3_k(const float* __restrict__ w, const float* __restrict__ bias) {
    extern __shared__ float sm[];
    float* in_s = sm;            // 12*32*84 = 32256
    float* w_s  = sm + 32256;    // 288*68, [ic*9+kk][oc]
    int b0 = blockIdx.x * 12, tid = threadIdx.x, nt = blockDim.x;
    int nimg = min(12, NB - b0);
    float4* z4 = (float4*)in_s;
    for (int i = tid; i < 8064; i += nt) z4[i] = make_float4(0.f, 0.f, 0.f, 0.f);
    for (int i = tid; i < 18432; i += nt) {
        int oc = i & 63, rest = i >> 6;
        w_s[rest * 68 + oc] = w[oc * 288 + rest];
    }
    __syncthreads();
    for (int i = tid; i < nimg * 1568; i += nt) {
        int img = i / 1568, r = i % 1568;
        int ic = r / 49, q = r % 49, y = q / 7, xx = q % 7;
        in_s[(img * 32 + ic) * 84 + (y + 1) * 9 + (xx + 1)] = g_h2[(size_t)(b0 + img) * 1568 + r];
    }
    __syncthreads();
    int img = tid / 32, rr = tid % 32;
    if (img >= nimg) return;
    int p = rr & 15, half = rr >> 4;
    int oy = p >> 2, ox = p & 3;
    u64 acc[16];
    #pragma unroll
    for (int j = 0; j < 16; j++) acc[j] = pk2(bias[half * 32 + 2 * j], bias[half * 32 + 2 * j + 1]);
    for (int ic = 0; ic < 32; ic++) {
        const float* xs = in_s + (img * 32 + ic) * 84 + (oy * 2) * 9 + ox * 2;
        const float* wb = w_s + (ic * 9) * 68 + half * 32;
        #pragma unroll
        for (int kk = 0; kk < 9; kk++) {
            u64 xd = dup2(xs[(kk / 3) * 9 + (kk % 3)]);
            const ulonglong2* wq = (const ulonglong2*)(wb + kk * 68);
            #pragma unroll
            for (int v = 0; v < 8; v++) {
                ulonglong2 wv = wq[v];
                fm2(acc[2 * v], xd, wv.x); fm2(acc[2 * v + 1], xd, wv.y);
            }
        }
    }
    #pragma unroll
    for (int j = 0; j < 16; j++) {
        float lo, hi; up2(acc[j], lo, hi);
        g_h3[(size_t)((b0 + img) * 64 + half * 32 + 2 * j)     * 16 + p] = fmaxf(lo, 0.f);
        g_h3[(size_t)((b0 + img) * 64 + half * 32 + 2 * j + 1) * 16 + p] = fmaxf(hi, 0.f);
    }
}

// ---------------- NT GEMM: BM=64, BN=64, BK=16, 256 threads, 4x4 register tile ----------------
__global__ void gemm_k(const float* __restrict__ A, const float* __restrict__ W,
                       const float* __restrict__ bias, float* __restrict__ C,
                       int M, int N, int K, int relu) {
    __shared__ float As[16 * 68];
    __shared__ float Ws[16 * 68];
    int tid = threadIdx.x, tx = tid & 15, ty = tid >> 4;   // tx 0..15 (n), ty 0..15 (m)
    int m0 = blockIdx.y * 64, n0 = blockIdx.x * 64;
    u64 acc[4][2] = {};
    for (int kt = 0; kt < K; kt += 16) {
        #pragma unroll
        for (int i = 0; i < 4; i++) {
            int idx = tid + i * 256;
            int k = idx & 15, m = idx >> 4;
            As[k * 68 + m] = A[(size_t)(m0 + m) * K + kt + k];
        }
        #pragma unroll
        for (int i = 0; i < 4; i++) {
            int idx = tid + i * 256;
            int k = idx & 15, n = idx >> 4;
            Ws[k * 68 + n] = W[(size_t)(n0 + n) * K + kt + k];
        }
        __syncthreads();
        #pragma unroll
        for (int kk = 0; kk < 16; kk++) {
            float4 a = *(const float4*)&As[kk * 68 + ty * 4];
            ulonglong2 bv = *(const ulonglong2*)&Ws[kk * 68 + tx * 4];
            u64 a0 = dup2(a.x), a1 = dup2(a.y), a2 = dup2(a.z), a3 = dup2(a.w);
            fm2(acc[0][0], a0, bv.x); fm2(acc[0][1], a0, bv.y);
            fm2(acc[1][0], a1, bv.x); fm2(acc[1][1], a1, bv.y);
            fm2(acc[2][0], a2, bv.x); fm2(acc[2][1], a2, bv.y);
            fm2(acc[3][0], a3, bv.x); fm2(acc[3][1], a3, bv.y);
        }
        __syncthreads();
    }
    #pragma unroll
    for (int i = 0; i < 4; i++) {
        int m = m0 + ty * 4 + i;
        #pragma unroll
        for (int jp = 0; jp < 2; jp++) {
            float lo, hi; up2(acc[i][jp], lo, hi);
            int n = n0 + tx * 4 + 2 * jp;
            float v0 = lo + bias[n], v1 = hi + bias[n + 1];
            if (relu) { v0 = fmaxf(v0, 0.f); v1 = fmaxf(v1, 0.f); }
            C[(size_t)m * N + n] = v0;
            C[(size_t)m * N + n + 1] = v1;
        }
    }
}

// ---------------- latent ----------------
__global__ void latent_k(const float* __restrict__ w_mu, const float* __restrict__ b_mu,
                         const float* __restrict__ w_ls, const float* __restrict__ b_ls,
                         const float* __restrict__ eps, float* __restrict__ out) {
    int idx = blockIdx.x * 256 + threadIdx.x;
    if (idx >= NB * 20) return;
    int b = idx / 20, l = idx % 20;
    const float4* h4 = (const float4*)(g_hf + (size_t)b * 256);
    const float4* wm = (const float4*)(w_mu + (size_t)l * 256);
    const float4* wl = (const float4*)(w_ls + (size_t)l * 256);
    float sm_ = 0.f, sl_ = 0.f;
    #pragma unroll 8
    for (int k = 0; k < 64; k++) {
        float4 h = h4[k], a = wm[k], c = wl[k];
        sm_ += h.x * a.x + h.y * a.y + h.z * a.z + h.w * a.w;
        sl_ += h.x * c.x + h.y * c.y + h.z * c.z + h.w * c.w;
    }
    float mu = sm_ + b_mu[l];
    float ls = sl_ + b_ls[l];
    out[MU_OFF + idx] = mu;
    out[LS_OFF + idx] = ls;
    float m = mu, s = ls;
    #pragma unroll 4
    for (int i = 0; i < 100; i++) {
        m = m + 0.1f * m;
        s = s + 0.05f * (expf(s) - 1.0f);
    }
    g_z[idx] = eps[idx] * expf(0.5f * s) + m;
}

// ---------------- fc2 ----------------
__global__ void fc2_k(const float* __restrict__ w, const float* __restrict__ bias) {
    int idx = blockIdx.x * 256 + threadIdx.x;
    if (idx >= NB * 256) return;
    int b = idx >> 8, o = idx & 255;
    const float* z = g_z + (size_t)b * 20;
    const float* wr = w + (size_t)o * 20;
    float acc = bias[o];
    #pragma unroll
    for (int k = 0; k < 20; k++) acc += z[k] * wr[k];
    g_f2[idx] = fmaxf(acc, 0.f);
}

// ---------------- deconv1: 6 img/block, thread = (image-pair, p, half:16oc) ----------------
__global__ void deconv1_k(const float* __restrict__ w, const float* __restrict__ bias) {
    extern __shared__ float sm[];
    float* in_s = sm;            // 6*1024 = 6144
    float* w_s  = sm + 6144;     // 576*36 = 20736, [ic*9+kk][oc]
    int b0 = blockIdx.x * 6, tid = threadIdx.x, nt = blockDim.x;
    int nimg = min(6, NB - b0);
    for (int i = tid; i < nimg * 1024; i += nt) in_s[i] = g_f3[(size_t)b0 * 1024 + i];
    for (int i = tid; i < 18432; i += nt) {
        int oc = i & 31, rest = i >> 5;
        int ic = rest / 9, kk = rest % 9;
        w_s[rest * 36 + oc] = w[ic * 288 + oc * 9 + kk];
    }
    __syncthreads();
    if (tid >= 294) return;
    int ip = tid / 98, rr = tid % 98;
    int p = rr % 49, half = rr / 49;
    int imgA = 2 * ip, imgB = 2 * ip + 1;
    int vA = imgA < nimg, vB = imgB < nimg;
    if (!vA) return;
    int imgBc = vB ? imgB : imgA;
    int oy = p / 7, ox = p % 7;
    int kyA = (oy & 1) ? 0 : 1;
    int iyA = (oy + 1 - kyA) >> 1;
    int vyB = oy & 1;
    int iyB = (oy >= 1) ? ((oy - 1) >> 1) : 0;
    int kxA = (ox & 1) ? 0 : 1;
    int ixA = (ox + 1 - kxA) >> 1;
    int vxB = ox & 1;
    int ixB = (ox >= 1) ? ((ox - 1) >> 1) : 0;
    int kyT[2] = {kyA, 2}, iyT[2] = {iyA, iyB};
    int kxT[2] = {kxA, 2}, ixT[2] = {ixA, ixB};
    int vy[2] = {1, vyB}, vx[2] = {1, vxB};
    u64 accA[8], accB[8];
    #pragma unroll
    for (int j = 0; j < 8; j++) {
        u64 bv = pk2(bias[half * 16 + 2 * j], bias[half * 16 + 2 * j + 1]);
        accA[j] = bv; accB[j] = bv;
    }
    for (int ic = 0; ic < 64; ic++) {
        const float* xsA = in_s + imgA * 1024 + ic * 16;
        const float* xsB = in_s + imgBc * 1024 + ic * 16;
        #pragma unroll
        for (int a = 0; a < 2; a++) {
            #pragma unroll
            for (int bb = 0; bb < 2; bb++) {
                int valid = vy[a] & vx[bb];
                int off = iyT[a] * 4 + ixT[bb];
                u64 xdA = dup2(valid ? xsA[off] : 0.f);
                u64 xdB = dup2(valid ? xsB[off] : 0.f);
                const ulonglong2* wq = (const ulonglong2*)(w_s + (ic * 9 + kyT[a] * 3 + kxT[bb]) * 36 + half * 16);
                ulonglong2 w0 = wq[0], w1 = wq[1], w2 = wq[2], w3 = wq[3];
                fm2(accA[0], xdA, w0.x); fm2(accA[1], xdA, w0.y);
                fm2(accA[2], xdA, w1.x); fm2(accA[3], xdA, w1.y);
                fm2(accA[4], xdA, w2.x); fm2(accA[5], xdA, w2.y);
                fm2(accA[6], xdA, w3.x); fm2(accA[7], xdA, w3.y);
                fm2(accB[0], xdB, w0.x); fm2(accB[1], xdB, w0.y);
                fm2(accB[2], xdB, w1.x); fm2(accB[3], xdB, w1.y);
                fm2(accB[4], xdB, w2.x); fm2(accB[5], xdB, w2.y);
                fm2(accB[6], xdB, w3.x); fm2(accB[7], xdB, w3.y);
            }
        }
    }
    #pragma unroll
    for (int j = 0; j < 8; j++) {
        float lo, hi; up2(accA[j], lo, hi);
        g_u1[(size_t)((b0 + imgA) * 32 + half * 16 + 2 * j)     * 49 + p] = fmaxf(lo, 0.f);
        g_u1[(size_t)((b0 + imgA) * 32 + half * 16 + 2 * j + 1) * 49 + p] = fmaxf(hi, 0.f);
    }
    if (vB) {
        #pragma unroll
        for (int j = 0; j < 8; j++) {
            float lo, hi; up2(accB[j], lo, hi);
            g_u1[(size_t)((b0 + imgB) * 32 + half * 16 + 2 * j)     * 49 + p] = fmaxf(lo, 0.f);
            g_u1[(size_t)((b0 + imgB) * 32 + half * 16 + 2 * j + 1) * 49 + p] = fmaxf(hi, 0.f);
        }
    }
}

// ---------------- deconv2: 2 img/block, thread = (p, half:16oc) computing BOTH images ----------------
__global__ void deconv2_k(const float* __restrict__ w, const float* __restrict__ bias) {
    extern __shared__ float sm[];
    float* in_s = sm;            // 2*32*84 = 5376
    float* w_s  = sm + 5376;     // 512*36, [ic*16+kk][oc]
    int b0 = blockIdx.x * 2, tid = threadIdx.x, nt = blockDim.x;
    float4* z4 = (float4*)in_s;
    for (int i = tid; i < 1344; i += nt) z4[i] = make_float4(0.f, 0.f, 0.f, 0.f);
    for (int i = tid; i < 16384; i += nt) {
        int oc = i & 31, rest = i >> 5;
        w_s[rest * 36 + oc] = w[(rest >> 4) * 512 + oc * 16 + (rest & 15)];
    }
    __syncthreads();
    for (int i = tid; i < 2 * 1568; i += nt) {
        int img = i / 1568, r = i % 1568;
        int ic = r / 49, q = r % 49, y = q / 7, xx = q % 7;
        in_s[(img * 32 + ic) * 84 + (y + 1) * 9 + (xx + 1)] = g_u1[(size_t)(b0 + img) * 1568 + r];
    }
    __syncthreads();
    if (tid >= 392) return;
    int p = tid % 196, half = tid / 196;
    int oy = p / 14, ox = p % 14;
    int c = (oy + 1) & 1;
    int r0 = ((oy + 1 - c) >> 1) + 1;
    int d = (ox + 1) & 1;
    int c0 = ((ox + 1 - d) >> 1) + 1;
    u64 accA[8], accB[8];
    #pragma unroll
    for (int j = 0; j < 8; j++) {
        u64 bv = pk2(bias[half * 16 + 2 * j], bias[half * 16 + 2 * j + 1]);
        accA[j] = bv; accB[j] = bv;
    }
    for (int ic = 0; ic < 32; ic++) {
        const float* xsA = in_s + ic * 84;
        const float* xsB = in_s + (32 + ic) * 84;
        #pragma unroll
        for (int a = 0; a < 2; a++) {
            #pragma unroll
            for (int bb = 0; bb < 2; bb++) {
                int off = (r0 - a) * 9 + (c0 - bb);
                u64 xdA = dup2(xsA[off]);
                u64 xdB = dup2(xsB[off]);
                int kk = (c + 2 * a) * 4 + (d + 2 * bb);
                const ulonglong2* wq = (const ulonglong2*)(w_s + (ic * 16 + kk) * 36 + half * 16);
                ulonglong2 w0 = wq[0], w1 = wq[1], w2 = wq[2], w3 = wq[3];
                fm2(accA[0], xdA, w0.x); fm2(accA[1], xdA, w0.y);
                fm2(accA[2], xdA, w1.x); fm2(accA[3], xdA, w1.y);
                fm2(accA[4], xdA, w2.x); fm2(accA[5], xdA, w2.y);
                fm2(accA[6], xdA, w3.x); fm2(accA[7], xdA, w3.y);
                fm2(accB[0], xdB, w0.x); fm2(accB[1], xdB, w0.y);
                fm2(accB[2], xdB, w1.x); fm2(accB[3], xdB, w1.y);
                fm2(accB[4], xdB, w2.x); fm2(accB[5], xdB, w2.y);
                fm2(accB[6], xdB, w3.x); fm2(accB[7], xdB, w3.y);
            }
        }
    }
    #pragma unroll
    for (int j = 0; j < 8; j++) {
        float lo, hi; up2(accA[j], lo, hi);
        g_u2[(size_t)(b0 * 32 + half * 16 + 2 * j)     * 196 + p] = fmaxf(lo, 0.f);
        g_u2[(size_t)(b0 * 32 + half * 16 + 2 * j + 1) * 196 + p] = fmaxf(hi, 0.f);
    }
    #pragma unroll
    for (int j = 0; j < 8; j++) {
        float lo, hi; up2(accB[j], lo, hi);
        g_u2[(size_t)((b0 + 1) * 32 + half * 16 + 2 * j)     * 196 + p] = fmaxf(lo, 0.f);
        g_u2[(size_t)((b0 + 1) * 32 + half * 16 + 2 * j + 1) * 196 + p] = fmaxf(hi, 0.f);
    }
}

// ---------------- deconv3 ----------------
__global__ void deconv3_k(const float* __restrict__ w, const float* __restrict__ bias,
                          float* __restrict__ out) {
    extern __shared__ float sm[];
    float* in_s = sm;                    // 2*32*256 = 16384
    u64*   wpk  = (u64*)(sm + 16384);    // 256 u64
    int b0 = blockIdx.x * 2, tid = threadIdx.x, nt = blockDim.x;
    float4* z4 = (float4*)in_s;
    for (int i = tid; i < 4096; i += nt) z4[i] = make_float4(0.f, 0.f, 0.f, 0.f);
    for (int i = tid; i < 256; i += nt) {
        int t = i & 1, rest = i >> 1;
        int ic = rest & 31, ky = rest >> 5;
        wpk[(ky * 32 + ic) * 2 + t] = pk2(w[ic * 16 + ky * 4 + 2 * t + 1], w[ic * 16 + ky * 4 + 2 * t]);
    }
    __syncthreads();
    for (int i = tid; i < 2 * 6272; i += nt) {
        int img = i / 6272, r = i % 6272;
        int ic = r / 196, q = r % 196, y = q / 14, xx = q % 14;
        in_s[(img * 32 + ic) * 256 + (y + 1) * 16 + (xx + 1)] = g_u2[(size_t)(b0 + img) * 6272 + r];
    }
    __syncthreads();
    if (tid >= 392) return;
    int img = tid / 196, q = tid % 196;
    int oy = q / 7, t = q % 7;
    int mm = 2 * t;
    int c = (oy + 1) & 1;
    int r0 = ((oy + 1 - c) >> 1) + 1;
    float b0v = bias[0];
    u64 p1 = pk2(b0v, b0v), p2 = pk2(0.f, 0.f);
    for (int ic = 0; ic < 32; ic++) {
        const float* xs = in_s + (img * 32 + ic) * 256;
        const float* row0 = xs + r0 * 16 + mm;
        const float* row1 = row0 - 16;
        float i00 = row0[0], i01 = row0[1], i02 = row0[2], i03 = row0[3];
        float i10 = row1[0], i11 = row1[1], i12 = row1[2], i13 = row1[3];
        u64 q01a = pk2(i00, i01), q12a = pk2(i01, i02), q23a = pk2(i02, i03);
        u64 q01b = pk2(i10, i11), q12b = pk2(i11, i12), q23b = pk2(i12, i13);
        ulonglong2 wa = *(const ulonglong2*)&wpk[(c * 32 + ic) * 2];
        ulonglong2 wb = *(const ulonglong2*)&wpk[((c + 2) * 32 + ic) * 2];
        fm2(p1, q12a, wa.x); fm2(p1, q01a, wa.y);
        fm2(p2, q23a, wa.x); fm2(p2, q12a, wa.y);
        fm2(p1, q12b, wb.x); fm2(p1, q01b, wb.y);
        fm2(p2, q23b, wb.x); fm2(p2, q12b, wb.y);
    }
    float v0, v1, v2, v3;
    up2(p1, v0, v1); up2(p2, v2, v3);
    v2 += b0v; v3 += b0v;
    size_t ob = (size_t)(b0 + img) * 784 + oy * 28 + 4 * t;
    out[ob]     = 1.0f / (1.0f + expf(-v0));
    out[ob + 1] = 1.0f / (1.0f + expf(-v1));
    out[ob + 2] = 1.0f / (1.0f + expf(-v2));
    out[ob + 3] = 1.0f / (1.0f + expf(-v3));
}

// ---------------- launch ----------------
extern "C" void kernel_launch(void* const* d_in, const int* in_sizes, int n_in,
                              void* d_out, int out_size) {
    const float* x     = (const float*)d_in[0];
    const float* eps   = (const float*)d_in[1];
    const float* w_c1  = (const float*)d_in[2];
    const float* b_c1  = (const float*)d_in[3];
    const float* w_c2  = (const float*)d_in[4];
    const float* b_c2  = (const float*)d_in[5];
    const float* w_c3  = (const float*)d_in[6];
    const float* b_c3  = (const float*)d_in[7];
    const float* w_fc1 = (const float*)d_in[8];
    const float* b_fc1 = (const float*)d_in[9];
    const float* w_mu  = (const float*)d_in[10];
    const float* b_mu  = (const float*)d_in[11];
    const float* w_ls  = (const float*)d_in[12];
    const float* b_ls  = (const float*)d_in[13];
    const float* w_fc2 = (const float*)d_in[14];
    const float* b_fc2 = (const float*)d_in[15];
    const float* w_fc3 = (const float*)d_in[16];
    const float* b_fc3 = (const float*)d_in[17];
    const float* w_d1  = (const float*)d_in[18];
    const float* b_d1  = (const float*)d_in[19];
    const float* w_d2  = (const float*)d_in[20];
    const float* b_d2  = (const float*)d_in[21];
    const float* w_d3  = (const float*)d_in[22];
    const float* b_d3  = (const float*)d_in[23];
    float* out = (float*)d_out;

    cudaFuncSetAttribute(conv2_k,   cudaFuncAttributeMaxDynamicSharedMemorySize, 221184);
    cudaFuncSetAttribute(conv3_k,   cudaFuncAttributeMaxDynamicSharedMemorySize, 207360);
    cudaFuncSetAttribute(deconv1_k, cudaFuncAttributeMaxDynamicSharedMemorySize, 107520);
    cudaFuncSetAttribute(deconv2_k, cudaFuncAttributeMaxDynamicSharedMemorySize, 95232);
    cudaFuncSetAttribute(deconv3_k, cudaFuncAttributeMaxDynamicSharedMemorySize, 69632);

    float *p_h3, *p_hf, *p_f2, *p_f3;
    cudaGetSymbolAddress((void**)&p_h3, g_h3);
    cudaGetSymbolAddress((void**)&p_hf, g_hf);
    cudaGetSymbolAddress((void**)&p_f2, g_f2);
    cudaGetSymbolAddress((void**)&p_f3, g_f3);

    conv1_k<<<NB, 256, (784 + 512) * 4>>>(x, w_c1, b_c1);
    conv2_k<<<NB / 4, 416, 221184>>>(w_c2, b_c2);
    conv3_k<<<(NB + 11) / 12, 384, 207360>>>(w_c3, b_c3);
    gemm_k<<<dim3(256 / 64, NB / 64), 256>>>(p_h3, w_fc1, b_fc1, p_hf, NB, 256, 1024, 1);
    latent_k<<<(NB * 20 + 255) / 256, 256>>>(w_mu, b_mu, w_ls, b_ls, eps, out);
    fc2_k<<<(NB * 256 + 255) / 256, 256>>>(w_fc2, b_fc2);
    gemm_k<<<dim3(1024 / 64, NB / 64), 256>>>(p_f2, w_fc3, b_fc3, p_f3, NB, 1024, 256, 1);
    deconv1_k<<<(NB + 5) / 6, 320, 107520>>>(w_d1, b_d1);
    deconv2_k<<<NB / 2, 416, 95232>>>(w_d2, b_d2);
    deconv3_k<<<NB / 2, 416, 69632>>>(w_d3, b_d3, out);
}

// round 14
// speedup vs baseline: 1.4317x; 1.0856x over previous
#include <cuda_runtime.h>
#include <math.h>

#define NB 4096
typedef unsigned long long u64;

__device__ __forceinline__ u64 pk2(float lo, float hi) {
    u64 r; asm("mov.b64 %0,{%1,%2};" : "=l"(r) : "f"(lo), "f"(hi)); return r;
}
__device__ __forceinline__ u64 dup2(float x) { return pk2(x, x); }
__device__ __forceinline__ void fm2(u64& d, u64 a, u64 b) {
    asm("fma.rn.f32x2 %0,%1,%2,%0;" : "+l"(d) : "l"(a), "l"(b));
}
__device__ __forceinline__ void up2(u64 v, float& a, float& b) {
    asm("mov.b64 {%0,%1},%2;" : "=f"(a), "=f"(b) : "l"(v));
}

// ---------------- scratch ----------------
__device__ float g_h1[NB * 32 * 196];
__device__ float g_h2[NB * 32 * 49];
__device__ float g_h3[NB * 1024];
__device__ float g_hf[NB * 256];
__device__ float g_z [NB * 20];
__device__ float g_f2[NB * 256];
__device__ float g_f3[NB * 1024];
__device__ float g_u1[NB * 32 * 49];
__device__ float g_u2[NB * 32 * 196];

// pre-transposed weights: [rest][oc] so per-block staging is coalesced
__device__ float g_w2t [16384];   // conv2:   [ic*16+kk][oc32]
__device__ float g_w3t [18432];   // conv3:   [ic*9+kk][oc64]
__device__ float g_wd1t[18432];   // deconv1: [ic*9+kk][oc32]
__device__ float g_wd2t[16384];   // deconv2: [ic*16+kk][oc32]

#define MU_OFF   (NB * 784)
#define LS_OFF   (NB * 784 + NB * 20)

// ---------------- weight prep: one-time transposes (uncoalesced reads happen ONCE) ----------------
__global__ void prep_w(const float* __restrict__ w2, const float* __restrict__ w3,
                       const float* __restrict__ wd1, const float* __restrict__ wd2) {
    int i = blockIdx.x * 256 + threadIdx.x;
    if (i < 16384) {
        int oc = i & 31, rest = i >> 5;
        g_w2t[rest * 32 + oc] = w2[oc * 512 + rest];
        g_wd2t[rest * 32 + oc] = wd2[(rest >> 4) * 512 + oc * 16 + (rest & 15)];
    }
    if (i < 18432) {
        int oc64 = i & 63, rest64 = i >> 6;
        g_w3t[rest64 * 64 + oc64] = w3[oc64 * 288 + rest64];
        int oc = i & 31, rest = i >> 5;
        int ic = rest / 9, kk = rest % 9;
        g_wd1t[rest * 32 + oc] = wd1[ic * 288 + oc * 9 + kk];
    }
}

// ---------------- conv1 ----------------
__global__ void conv1_k(const float* __restrict__ x, const float* __restrict__ w,
                        const float* __restrict__ bias) {
    extern __shared__ float sm[];
    float* in_s = sm;          // 784
    float* w_s  = sm + 784;    // 512, [kk][oc]
    int b = blockIdx.x, tid = threadIdx.x;
    const float* xin = x + b * 784;
    for (int i = tid; i < 784; i += 256) in_s[i] = xin[i];
    for (int i = tid; i < 512; i += 256) { int oc = i & 31, kk = i >> 5; w_s[kk * 32 + oc] = w[oc * 16 + kk]; }
    __syncthreads();
    for (int u = tid; u < 784; u += 256) {
        int p = u >> 2, g = u & 3;
        int oy = p / 14, ox = p % 14;
        u64 acc[4];
        #pragma unroll
        for (int j = 0; j < 4; j++) acc[j] = pk2(bias[g * 8 + 2 * j], bias[g * 8 + 2 * j + 1]);
        #pragma unroll
        for (int ky = 0; ky < 4; ky++) {
            int iy = oy * 2 - 1 + ky;
            if (iy < 0 || iy >= 28) continue;
            #pragma unroll
            for (int kx = 0; kx < 4; kx++) {
                int ix = ox * 2 - 1 + kx;
                if (ix < 0 || ix >= 28) continue;
                u64 xd = dup2(in_s[iy * 28 + ix]);
                const ulonglong2* wq = (const ulonglong2*)(w_s + (ky * 4 + kx) * 32 + g * 8);
                ulonglong2 w0 = wq[0];
                fm2(acc[0], xd, w0.x); fm2(acc[1], xd, w0.y);
                ulonglong2 w1 = wq[1];
                fm2(acc[2], xd, w1.x); fm2(acc[3], xd, w1.y);
            }
        }
        #pragma unroll
        for (int j = 0; j < 4; j++) {
            float lo, hi; up2(acc[j], lo, hi);
            g_h1[(size_t)(b * 32 + g * 8 + 2 * j)     * 196 + p] = fmaxf(lo, 0.f);
            g_h1[(size_t)(b * 32 + g * 8 + 2 * j + 1) * 196 + p] = fmaxf(hi, 0.f);
        }
    }
}

// ---------------- conv2: 4 img/block, thread = (img, pixel-pair, quarter:8oc) ----------------
__global__ void conv2_k(const float* __restrict__ bias) {
    extern __shared__ float sm[];
    float* in_s = sm;            // 4*32*288 = 36864
    float* w_s  = sm + 36864;    // 512*36, [ic*16+kk][oc]
    int b0 = blockIdx.x * 4, tid = threadIdx.x, nt = blockDim.x;
    float4* z4 = (float4*)in_s;
    for (int i = tid; i < 9216; i += nt) z4[i] = make_float4(0.f, 0.f, 0.f, 0.f);
    for (int i = tid; i < 16384; i += nt)
        w_s[(i >> 5) * 36 + (i & 31)] = g_w2t[i];   // coalesced read, conflict-free write
    __syncthreads();
    for (int i = tid; i < 4 * 6272; i += nt) {
        int img = i / 6272, r = i % 6272;
        int ic = r / 196, q = r % 196, y = q / 14, xx = q % 14;
        in_s[(img * 32 + ic) * 288 + (y + 1) * 18 + (xx + 1)] = g_h1[(size_t)(b0 + img) * 6272 + r];
    }
    __syncthreads();
    if (tid >= 400) return;
    int img = tid / 100, rr = tid % 100;
    int pp = rr % 25, q = rr / 25;
    int pA = pp, pB = pp + 25;
    int validB = (pB < 49);
    int pBc = validB ? pB : 24;
    int oyA = pA / 7, oxA = pA % 7;
    int oyB = pBc / 7, oxB = pBc % 7;
    u64 accA[4], accB[4];
    #pragma unroll
    for (int j = 0; j < 4; j++) {
        u64 bv = pk2(bias[q * 8 + 2 * j], bias[q * 8 + 2 * j + 1]);
        accA[j] = bv; accB[j] = bv;
    }
    for (int ic = 0; ic < 32; ic++) {
        const float* base = in_s + (img * 32 + ic) * 288;
        const float* xsA = base + (oyA * 2) * 18 + oxA * 2;
        const float* xsB = base + (oyB * 2) * 18 + oxB * 2;
        const float* wb = w_s + (ic * 16) * 36 + q * 8;
        #pragma unroll
        for (int kk = 0; kk < 16; kk++) {
            u64 xdA = dup2(xsA[(kk >> 2) * 18 + (kk & 3)]);
            u64 xdB = dup2(xsB[(kk >> 2) * 18 + (kk & 3)]);
            const ulonglong2* wq = (const ulonglong2*)(wb + kk * 36);
            ulonglong2 w0 = wq[0], w1 = wq[1];
            fm2(accA[0], xdA, w0.x); fm2(accA[1], xdA, w0.y);
            fm2(accA[2], xdA, w1.x); fm2(accA[3], xdA, w1.y);
            fm2(accB[0], xdB, w0.x); fm2(accB[1], xdB, w0.y);
            fm2(accB[2], xdB, w1.x); fm2(accB[3], xdB, w1.y);
        }
    }
    #pragma unroll
    for (int j = 0; j < 4; j++) {
        float lo, hi; up2(accA[j], lo, hi);
        g_h2[(size_t)((b0 + img) * 32 + q * 8 + 2 * j)     * 49 + pA] = fmaxf(lo, 0.f);
        g_h2[(size_t)((b0 + img) * 32 + q * 8 + 2 * j + 1) * 49 + pA] = fmaxf(hi, 0.f);
    }
    if (validB) {
        #pragma unroll
        for (int j = 0; j < 4; j++) {
            float lo, hi; up2(accB[j], lo, hi);
            g_h2[(size_t)((b0 + img) * 32 + q * 8 + 2 * j)     * 49 + pB] = fmaxf(lo, 0.f);
            g_h2[(size_t)((b0 + img) * 32 + q * 8 + 2 * j + 1) * 49 + pB] = fmaxf(hi, 0.f);
        }
    }
}

// ---------------- conv3: 12 img/block, 384 threads, acc 32 oc ----------------
__global__ void conv3_k(const float* __restrict__ bias) {
    extern __shared__ float sm[];
    float* in_s = sm;            // 12*32*84 = 32256
    float* w_s  = sm + 32256;    // 288*68, [ic*9+kk][oc]
    int b0 = blockIdx.x * 12, tid = threadIdx.x, nt = blockDim.x;
    int nimg = min(12, NB - b0);
    float4* z4 = (float4*)in_s;
    for (int i = tid; i < 8064; i += nt) z4[i] = make_float4(0.f, 0.f, 0.f, 0.f);
    for (int i = tid; i < 18432; i += nt)
        w_s[(i >> 6) * 68 + (i & 63)] = g_w3t[i];
    __syncthreads();
    for (int i = tid; i < nimg * 1568; i += nt) {
        int img = i / 1568, r = i % 1568;
        int ic = r / 49, q = r % 49, y = q / 7, xx = q % 7;
        in_s[(img * 32 + ic) * 84 + (y + 1) * 9 + (xx + 1)] = g_h2[(size_t)(b0 + img) * 1568 + r];
    }
    __syncthreads();
    int img = tid / 32, rr = tid % 32;
    if (img >= nimg) return;
    int p = rr & 15, half = rr >> 4;
    int oy = p >> 2, ox = p & 3;
    u64 acc[16];
    #pragma unroll
    for (int j = 0; j < 16; j++) acc[j] = pk2(bias[half * 32 + 2 * j], bias[half * 32 + 2 * j + 1]);
    for (int ic = 0; ic < 32; ic++) {
        const float* xs = in_s + (img * 32 + ic) * 84 + (oy * 2) * 9 + ox * 2;
        const float* wb = w_s + (ic * 9) * 68 + half * 32;
        #pragma unroll
        for (int kk = 0; kk < 9; kk++) {
            u64 xd = dup2(xs[(kk / 3) * 9 + (kk % 3)]);
            const ulonglong2* wq = (const ulonglong2*)(wb + kk * 68);
            #pragma unroll
            for (int v = 0; v < 8; v++) {
                ulonglong2 wv = wq[v];
                fm2(acc[2 * v], xd, wv.x); fm2(acc[2 * v + 1], xd, wv.y);
            }
        }
    }
    #pragma unroll
    for (int j = 0; j < 16; j++) {
        float lo, hi; up2(acc[j], lo, hi);
        g_h3[(size_t)((b0 + img) * 64 + half * 32 + 2 * j)     * 16 + p] = fmaxf(lo, 0.f);
        g_h3[(size_t)((b0 + img) * 64 + half * 32 + 2 * j + 1) * 16 + p] = fmaxf(hi, 0.f);
    }
}

// ---------------- NT GEMM: BM=64, BN=64, BK=16, 256 threads, 4x4 register tile ----------------
__global__ void gemm_k(const float* __restrict__ A, const float* __restrict__ W,
                       const float* __restrict__ bias, float* __restrict__ C,
                       int M, int N, int K, int relu) {
    __shared__ float As[16 * 68];
    __shared__ float Ws[16 * 68];
    int tid = threadIdx.x, tx = tid & 15, ty = tid >> 4;
    int m0 = blockIdx.y * 64, n0 = blockIdx.x * 64;
    u64 acc[4][2] = {};
    for (int kt = 0; kt < K; kt += 16) {
        #pragma unroll
        for (int i = 0; i < 4; i++) {
            int idx = tid + i * 256;
            int k = idx & 15, m = idx >> 4;
            As[k * 68 + m] = A[(size_t)(m0 + m) * K + kt + k];
        }
        #pragma unroll
        for (int i = 0; i < 4; i++) {
            int idx = tid + i * 256;
            int k = idx & 15, n = idx >> 4;
            Ws[k * 68 + n] = W[(size_t)(n0 + n) * K + kt + k];
        }
        __syncthreads();
        #pragma unroll
        for (int kk = 0; kk < 16; kk++) {
            float4 a = *(const float4*)&As[kk * 68 + ty * 4];
            ulonglong2 bv = *(const ulonglong2*)&Ws[kk * 68 + tx * 4];
            u64 a0 = dup2(a.x), a1 = dup2(a.y), a2 = dup2(a.z), a3 = dup2(a.w);
            fm2(acc[0][0], a0, bv.x); fm2(acc[0][1], a0, bv.y);
            fm2(acc[1][0], a1, bv.x); fm2(acc[1][1], a1, bv.y);
            fm2(acc[2][0], a2, bv.x); fm2(acc[2][1], a2, bv.y);
            fm2(acc[3][0], a3, bv.x); fm2(acc[3][1], a3, bv.y);
        }
        __syncthreads();
    }
    #pragma unroll
    for (int i = 0; i < 4; i++) {
        int m = m0 + ty * 4 + i;
        #pragma unroll
        for (int jp = 0; jp < 2; jp++) {
            float lo, hi; up2(acc[i][jp], lo, hi);
            int n = n0 + tx * 4 + 2 * jp;
            float v0 = lo + bias[n], v1 = hi + bias[n + 1];
            if (relu) { v0 = fmaxf(v0, 0.f); v1 = fmaxf(v1, 0.f); }
            C[(size_t)m * N + n] = v0;
            C[(size_t)m * N + n + 1] = v1;
        }
    }
}

// ---------------- latent ----------------
__global__ void latent_k(const float* __restrict__ w_mu, const float* __restrict__ b_mu,
                         const float* __restrict__ w_ls, const float* __restrict__ b_ls,
                         const float* __restrict__ eps, float* __restrict__ out) {
    int idx = blockIdx.x * 256 + threadIdx.x;
    if (idx >= NB * 20) return;
    int b = idx / 20, l = idx % 20;
    const float4* h4 = (const float4*)(g_hf + (size_t)b * 256);
    const float4* wm = (const float4*)(w_mu + (size_t)l * 256);
    const float4* wl = (const float4*)(w_ls + (size_t)l * 256);
    float sm_ = 0.f, sl_ = 0.f;
    #pragma unroll 8
    for (int k = 0; k < 64; k++) {
        float4 h = h4[k], a = wm[k], c = wl[k];
        sm_ += h.x * a.x + h.y * a.y + h.z * a.z + h.w * a.w;
        sl_ += h.x * c.x + h.y * c.y + h.z * c.z + h.w * c.w;
    }
    float mu = sm_ + b_mu[l];
    float ls = sl_ + b_ls[l];
    out[MU_OFF + idx] = mu;
    out[LS_OFF + idx] = ls;
    float m = mu, s = ls;
    #pragma unroll 4
    for (int i = 0; i < 100; i++) {
        m = m + 0.1f * m;
        s = s + 0.05f * (expf(s) - 1.0f);
    }
    g_z[idx] = eps[idx] * expf(0.5f * s) + m;
}

// ---------------- fc2 ----------------
__global__ void fc2_k(const float* __restrict__ w, const float* __restrict__ bias) {
    int idx = blockIdx.x * 256 + threadIdx.x;
    if (idx >= NB * 256) return;
    int b = idx >> 8, o = idx & 255;
    const float* z = g_z + (size_t)b * 20;
    const float* wr = w + (size_t)o * 20;
    float acc = bias[o];
    #pragma unroll
    for (int k = 0; k < 20; k++) acc += z[k] * wr[k];
    g_f2[idx] = fmaxf(acc, 0.f);
}

// ---------------- deconv1: 6 img/block, thread = (image-pair, p, half:16oc) ----------------
__global__ void deconv1_k(const float* __restrict__ bias) {
    extern __shared__ float sm[];
    float* in_s = sm;            // 6*1024 = 6144
    float* w_s  = sm + 6144;     // 576*36, [ic*9+kk][oc]
    int b0 = blockIdx.x * 6, tid = threadIdx.x, nt = blockDim.x;
    int nimg = min(6, NB - b0);
    for (int i = tid; i < nimg * 1024; i += nt) in_s[i] = g_f3[(size_t)b0 * 1024 + i];
    for (int i = tid; i < 18432; i += nt)
        w_s[(i >> 5) * 36 + (i & 31)] = g_wd1t[i];
    __syncthreads();
    if (tid >= 294) return;
    int ip = tid / 98, rr = tid % 98;
    int p = rr % 49, half = rr / 49;
    int imgA = 2 * ip, imgB = 2 * ip + 1;
    int vA = imgA < nimg, vB = imgB < nimg;
    if (!vA) return;
    int imgBc = vB ? imgB : imgA;
    int oy = p / 7, ox = p % 7;
    int kyA = (oy & 1) ? 0 : 1;
    int iyA = (oy + 1 - kyA) >> 1;
    int vyB = oy & 1;
    int iyB = (oy >= 1) ? ((oy - 1) >> 1) : 0;
    int kxA = (ox & 1) ? 0 : 1;
    int ixA = (ox + 1 - kxA) >> 1;
    int vxB = ox & 1;
    int ixB = (ox >= 1) ? ((ox - 1) >> 1) : 0;
    int kyT[2] = {kyA, 2}, iyT[2] = {iyA, iyB};
    int kxT[2] = {kxA, 2}, ixT[2] = {ixA, ixB};
    int vy[2] = {1, vyB}, vx[2] = {1, vxB};
    u64 accA[8], accB[8];
    #pragma unroll
    for (int j = 0; j < 8; j++) {
        u64 bv = pk2(bias[half * 16 + 2 * j], bias[half * 16 + 2 * j + 1]);
        accA[j] = bv; accB[j] = bv;
    }
    for (int ic = 0; ic < 64; ic++) {
        const float* xsA = in_s + imgA * 1024 + ic * 16;
        const float* xsB = in_s + imgBc * 1024 + ic * 16;
        #pragma unroll
        for (int a = 0; a < 2; a++) {
            #pragma unroll
            for (int bb = 0; bb < 2; bb++) {
                int valid = vy[a] & vx[bb];
                int off = iyT[a] * 4 + ixT[bb];
                u64 xdA = dup2(valid ? xsA[off] : 0.f);
                u64 xdB = dup2(valid ? xsB[off] : 0.f);
                const ulonglong2* wq = (const ulonglong2*)(w_s + (ic * 9 + kyT[a] * 3 + kxT[bb]) * 36 + half * 16);
                ulonglong2 w0 = wq[0], w1 = wq[1], w2 = wq[2], w3 = wq[3];
                fm2(accA[0], xdA, w0.x); fm2(accA[1], xdA, w0.y);
                fm2(accA[2], xdA, w1.x); fm2(accA[3], xdA, w1.y);
                fm2(accA[4], xdA, w2.x); fm2(accA[5], xdA, w2.y);
                fm2(accA[6], xdA, w3.x); fm2(accA[7], xdA, w3.y);
                fm2(accB[0], xdB, w0.x); fm2(accB[1], xdB, w0.y);
                fm2(accB[2], xdB, w1.x); fm2(accB[3], xdB, w1.y);
                fm2(accB[4], xdB, w2.x); fm2(accB[5], xdB, w2.y);
                fm2(accB[6], xdB, w3.x); fm2(accB[7], xdB, w3.y);
            }
        }
    }
    #pragma unroll
    for (int j = 0; j < 8; j++) {
        float lo, hi; up2(accA[j], lo, hi);
        g_u1[(size_t)((b0 + imgA) * 32 + half * 16 + 2 * j)     * 49 + p] = fmaxf(lo, 0.f);
        g_u1[(size_t)((b0 + imgA) * 32 + half * 16 + 2 * j + 1) * 49 + p] = fmaxf(hi, 0.f);
    }
    if (vB) {
        #pragma unroll
        for (int j = 0; j < 8; j++) {
            float lo, hi; up2(accB[j], lo, hi);
            g_u1[(size_t)((b0 + imgB) * 32 + half * 16 + 2 * j)     * 49 + p] = fmaxf(lo, 0.f);
            g_u1[(size_t)((b0 + imgB) * 32 + half * 16 + 2 * j + 1) * 49 + p] = fmaxf(hi, 0.f);
        }
    }
}

// ---------------- deconv2: 2 img/block, thread = (p, half:16oc) computing BOTH images ----------------
__global__ void deconv2_k(const float* __restrict__ bias) {
    extern __shared__ float sm[];
    float* in_s = sm;            // 2*32*84 = 5376
    float* w_s  = sm + 5376;     // 512*36, [ic*16+kk][oc]
    int b0 = blockIdx.x * 2, tid = threadIdx.x, nt = blockDim.x;
    float4* z4 = (float4*)in_s;
    for (int i = tid; i < 1344; i += nt) z4[i] = make_float4(0.f, 0.f, 0.f, 0.f);
    for (int i = tid; i < 16384; i += nt)
        w_s[(i >> 5) * 36 + (i & 31)] = g_wd2t[i];
    __syncthreads();
    for (int i = tid; i < 2 * 1568; i += nt) {
        int img = i / 1568, r = i % 1568;
        int ic = r / 49, q = r % 49, y = q / 7, xx = q % 7;
        in_s[(img * 32 + ic) * 84 + (y + 1) * 9 + (xx + 1)] = g_u1[(size_t)(b0 + img) * 1568 + r];
    }
    __syncthreads();
    if (tid >= 392) return;
    int p = tid % 196, half = tid / 196;
    int oy = p / 14, ox = p % 14;
    int c = (oy + 1) & 1;
    int r0 = ((oy + 1 - c) >> 1) + 1;
    int d = (ox + 1) & 1;
    int c0 = ((ox + 1 - d) >> 1) + 1;
    u64 accA[8], accB[8];
    #pragma unroll
    for (int j = 0; j < 8; j++) {
        u64 bv = pk2(bias[half * 16 + 2 * j], bias[half * 16 + 2 * j + 1]);
        accA[j] = bv; accB[j] = bv;
    }
    for (int ic = 0; ic < 32; ic++) {
        const float* xsA = in_s + ic * 84;
        const float* xsB = in_s + (32 + ic) * 84;
        #pragma unroll
        for (int a = 0; a < 2; a++) {
            #pragma unroll
            for (int bb = 0; bb < 2; bb++) {
                int off = (r0 - a) * 9 + (c0 - bb);
                u64 xdA = dup2(xsA[off]);
                u64 xdB = dup2(xsB[off]);
                int kk = (c + 2 * a) * 4 + (d + 2 * bb);
                const ulonglong2* wq = (const ulonglong2*)(w_s + (ic * 16 + kk) * 36 + half * 16);
                ulonglong2 w0 = wq[0], w1 = wq[1], w2 = wq[2], w3 = wq[3];
                fm2(accA[0], xdA, w0.x); fm2(accA[1], xdA, w0.y);
                fm2(accA[2], xdA, w1.x); fm2(accA[3], xdA, w1.y);
                fm2(accA[4], xdA, w2.x); fm2(accA[5], xdA, w2.y);
                fm2(accA[6], xdA, w3.x); fm2(accA[7], xdA, w3.y);
                fm2(accB[0], xdB, w0.x); fm2(accB[1], xdB, w0.y);
                fm2(accB[2], xdB, w1.x); fm2(accB[3], xdB, w1.y);
                fm2(accB[4], xdB, w2.x); fm2(accB[5], xdB, w2.y);
                fm2(accB[6], xdB, w3.x); fm2(accB[7], xdB, w3.y);
            }
        }
    }
    #pragma unroll
    for (int j = 0; j < 8; j++) {
        float lo, hi; up2(accA[j], lo, hi);
        g_u2[(size_t)(b0 * 32 + half * 16 + 2 * j)     * 196 + p] = fmaxf(lo, 0.f);
        g_u2[(size_t)(b0 * 32 + half * 16 + 2 * j + 1) * 196 + p] = fmaxf(hi, 0.f);
    }
    #pragma unroll
    for (int j = 0; j < 8; j++) {
        float lo, hi; up2(accB[j], lo, hi);
        g_u2[(size_t)((b0 + 1) * 32 + half * 16 + 2 * j)     * 196 + p] = fmaxf(lo, 0.f);
        g_u2[(size_t)((b0 + 1) * 32 + half * 16 + 2 * j + 1) * 196 + p] = fmaxf(hi, 0.f);
    }
}

// ---------------- deconv3 ----------------
__global__ void deconv3_k(const float* __restrict__ w, const float* __restrict__ bias,
                          float* __restrict__ out) {
    extern __shared__ float sm[];
    float* in_s = sm;                    // 2*32*256 = 16384
    u64*   wpk  = (u64*)(sm + 16384);    // 256 u64
    int b0 = blockIdx.x * 2, tid = threadIdx.x, nt = blockDim.x;
    float4* z4 = (float4*)in_s;
    for (int i = tid; i < 4096; i += nt) z4[i] = make_float4(0.f, 0.f, 0.f, 0.f);
    for (int i = tid; i < 256; i += nt) {
        int t = i & 1, rest = i >> 1;
        int ic = rest & 31, ky = rest >> 5;
        wpk[(ky * 32 + ic) * 2 + t] = pk2(w[ic * 16 + ky * 4 + 2 * t + 1], w[ic * 16 + ky * 4 + 2 * t]);
    }
    __syncthreads();
    for (int i = tid; i < 2 * 6272; i += nt) {
        int img = i / 6272, r = i % 6272;
        int ic = r / 196, q = r % 196, y = q / 14, xx = q % 14;
        in_s[(img * 32 + ic) * 256 + (y + 1) * 16 + (xx + 1)] = g_u2[(size_t)(b0 + img) * 6272 + r];
    }
    __syncthreads();
    if (tid >= 392) return;
    int img = tid / 196, q = tid % 196;
    int oy = q / 7, t = q % 7;
    int mm = 2 * t;
    int c = (oy + 1) & 1;
    int r0 = ((oy + 1 - c) >> 1) + 1;
    float b0v = bias[0];
    u64 p1 = pk2(b0v, b0v), p2 = pk2(0.f, 0.f);
    for (int ic = 0; ic < 32; ic++) {
        const float* xs = in_s + (img * 32 + ic) * 256;
        const float* row0 = xs + r0 * 16 + mm;
        const float* row1 = row0 - 16;
        float i00 = row0[0], i01 = row0[1], i02 = row0[2], i03 = row0[3];
        float i10 = row1[0], i11 = row1[1], i12 = row1[2], i13 = row1[3];
        u64 q01a = pk2(i00, i01), q12a = pk2(i01, i02), q23a = pk2(i02, i03);
        u64 q01b = pk2(i10, i11), q12b = pk2(i11, i12), q23b = pk2(i12, i13);
        ulonglong2 wa = *(const ulonglong2*)&wpk[(c * 32 + ic) * 2];
        ulonglong2 wb = *(const ulonglong2*)&wpk[((c + 2) * 32 + ic) * 2];
        fm2(p1, q12a, wa.x); fm2(p1, q01a, wa.y);
        fm2(p2, q23a, wa.x); fm2(p2, q12a, wa.y);
        fm2(p1, q12b, wb.x); fm2(p1, q01b, wb.y);
        fm2(p2, q23b, wb.x); fm2(p2, q12b, wb.y);
    }
    float v0, v1, v2, v3;
    up2(p1, v0, v1); up2(p2, v2, v3);
    v2 += b0v; v3 += b0v;
    size_t ob = (size_t)(b0 + img) * 784 + oy * 28 + 4 * t;
    out[ob]     = 1.0f / (1.0f + expf(-v0));
    out[ob + 1] = 1.0f / (1.0f + expf(-v1));
    out[ob + 2] = 1.0f / (1.0f + expf(-v2));
    out[ob + 3] = 1.0f / (1.0f + expf(-v3));
}

// ---------------- launch ----------------
extern "C" void kernel_launch(void* const* d_in, const int* in_sizes, int n_in,
                              void* d_out, int out_size) {
    const float* x     = (const float*)d_in[0];
    const float* eps   = (const float*)d_in[1];
    const float* w_c1  = (const float*)d_in[2];
    const float* b_c1  = (const float*)d_in[3];
    const float* w_c2  = (const float*)d_in[4];
    const float* b_c2  = (const float*)d_in[5];
    const float* w_c3  = (const float*)d_in[6];
    const float* b_c3  = (const float*)d_in[7];
    const float* w_fc1 = (const float*)d_in[8];
    const float* b_fc1 = (const float*)d_in[9];
    const float* w_mu  = (const float*)d_in[10];
    const float* b_mu  = (const float*)d_in[11];
    const float* w_ls  = (const float*)d_in[12];
    const float* b_ls  = (const float*)d_in[13];
    const float* w_fc2 = (const float*)d_in[14];
    const float* b_fc2 = (const float*)d_in[15];
    const float* w_fc3 = (const float*)d_in[16];
    const float* b_fc3 = (const float*)d_in[17];
    const float* w_d1  = (const float*)d_in[18];
    const float* b_d1  = (const float*)d_in[19];
    const float* w_d2  = (const float*)d_in[20];
    const float* b_d2  = (const float*)d_in[21];
    const float* w_d3  = (const float*)d_in[22];
    const float* b_d3  = (const float*)d_in[23];
    float* out = (float*)d_out;

    cudaFuncSetAttribute(conv2_k,   cudaFuncAttributeMaxDynamicSharedMemorySize, 221184);
    cudaFuncSetAttribute(conv3_k,   cudaFuncAttributeMaxDynamicSharedMemorySize, 207360);
    cudaFuncSetAttribute(deconv1_k, cudaFuncAttributeMaxDynamicSharedMemorySize, 107520);
    cudaFuncSetAttribute(deconv2_k, cudaFuncAttributeMaxDynamicSharedMemorySize, 95232);
    cudaFuncSetAttribute(deconv3_k, cudaFuncAttributeMaxDynamicSharedMemorySize, 69632);

    float *p_h3, *p_hf, *p_f2, *p_f3;
    cudaGetSymbolAddress((void**)&p_h3, g_h3);
    cudaGetSymbolAddress((void**)&p_hf, g_hf);
    cudaGetSymbolAddress((void**)&p_f2, g_f2);
    cudaGetSymbolAddress((void**)&p_f3, g_f3);

    prep_w<<<72, 256>>>(w_c2, w_c3, w_d1, w_d2);
    conv1_k<<<NB, 256, (784 + 512) * 4>>>(x, w_c1, b_c1);
    conv2_k<<<NB / 4, 416, 221184>>>(b_c2);
    conv3_k<<<(NB + 11) / 12, 384, 207360>>>(b_c3);
    gemm_k<<<dim3(256 / 64, NB / 64), 256>>>(p_h3, w_fc1, b_fc1, p_hf, NB, 256, 1024, 1);
    latent_k<<<(NB * 20 + 255) / 256, 256>>>(w_mu, b_mu, w_ls, b_ls, eps, out);
    fc2_k<<<(NB * 256 + 255) / 256, 256>>>(w_fc2, b_fc2);
    gemm_k<<<dim3(1024 / 64, NB / 64), 256>>>(p_f2, w_fc3, b_fc3, p_f3, NB, 1024, 256, 1);
    deconv1_k<<<(NB + 5) / 6, 320, 107520>>>(b_d1);
    deconv2_k<<<NB / 2, 416, 95232>>>(b_d2);
    deconv3_k<<<NB / 2, 416, 69632>>>(w_d3, b_d3, out);
}